// round 5
// baseline (speedup 1.0000x reference)
#include <cuda_runtime.h>
#include <cstdint>

#define N_NODES   100000
#define N_REL     8
#define IN_FEATS  64
#define HD        128
#define N_EDGES   800000
#define NEG_SLOPE 0.2f

#define EPB_HIST  1024
#define NBLK_HIST ((N_EDGES + EPB_HIST - 1) / EPB_HIST)   // 782
#define NB_D      ((N_NODES + 1023) / 1024)               // 98

typedef unsigned long long u64;
typedef unsigned int u32;

// ---------------- scratch ---------------------------------------------------
__device__ float g_p[N_EDGES * 4];
__device__ int   g_idx32;
__device__ int   g_eorder[N_EDGES];      // edges sorted by relation
__device__ int   g_edst[N_EDGES];        // edges sorted by dst
__device__ int   g_relcnt[8];
__device__ int   g_relcur[8];
__device__ int   g_roff[9];
__device__ int   g_woff[9];
__device__ int   g_dstcnt[N_NODES];
__device__ int   g_rowoff[N_NODES + 1];
__device__ int   g_dstcur[N_NODES];
__device__ int   g_bsumd[128];

// ---------------- helpers ---------------------------------------------------
__device__ __forceinline__ long long ldidx(const void* p, int i, int is32) {
    return is32 ? (long long)((const int*)p)[i] : ((const long long*)p)[i];
}
__device__ __forceinline__ float lrelu(float v) { return v > 0.0f ? v : NEG_SLOPE * v; }
// pack two floats -> bf16x2 (lo in low 16 bits)
__device__ __forceinline__ u32 bf2(float lo, float hi) {
    u32 r; asm("cvt.rn.bf16x2.f32 %0, %1, %2;" : "=r"(r) : "f"(hi), "f"(lo)); return r;
}
__device__ __forceinline__ void mma16(float* d, u32 a0, u32 a1, u32 a2, u32 a3,
                                      u32 b0, u32 b1) {
    asm volatile(
        "mma.sync.aligned.m16n8k16.row.col.f32.bf16.bf16.f32 "
        "{%0,%1,%2,%3}, {%4,%5,%6,%7}, {%8,%9}, {%0,%1,%2,%3};"
        : "+f"(d[0]), "+f"(d[1]), "+f"(d[2]), "+f"(d[3])
        : "r"(a0), "r"(a1), "r"(a2), "r"(a3), "r"(b0), "r"(b1));
}

// ---------------- kernel: zero sort scratch + detect index dtype ------------
__global__ void k_zinit(const void* src) {
    int i = blockIdx.x * blockDim.x + threadIdx.x;
    if (i < N_NODES) g_dstcnt[i] = 0;
    if (i < 8) g_relcnt[i] = 0;
    if (i == 0) {
        const long long* p = (const long long*)src;
        int bad = 0;
        for (int j = 0; j < 64; j++) {
            long long v = p[j];
            if (v < 0 || v >= N_NODES) bad = 1;
        }
        g_idx32 = bad;
    }
}

// ---------------- kernel: fused histogram (relation + dst) ------------------
__global__ void k_hist(const void* __restrict__ rtp, const void* __restrict__ dstp) {
    __shared__ int cnt[8];
    int tid = threadIdx.x;
    if (tid < 8) cnt[tid] = 0;
    __syncthreads();
    const int is32 = g_idx32;
    int base = blockIdx.x * EPB_HIST;
    for (int i = tid; i < EPB_HIST; i += 256) {
        int e = base + i;
        if (e < N_EDGES) {
            atomicAdd(&cnt[(int)ldidx(rtp, e, is32)], 1);
            atomicAdd(&g_dstcnt[(int)ldidx(dstp, e, is32)], 1);
        }
    }
    __syncthreads();
    if (tid < 8) atomicAdd(&g_relcnt[tid], cnt[tid]);
}

// ---------------- dst prefix scan (3 kernels; rscan fused into dscan2) ------
__global__ void k_dscan1() {
    __shared__ int ws[32];
    int t = threadIdx.x, b = blockIdx.x;
    int i = b * 1024 + t;
    int v = (i < N_NODES) ? g_dstcnt[i] : 0;
    int lane = t & 31, w = t >> 5;
    int x = v;
    #pragma unroll
    for (int o = 1; o < 32; o <<= 1) {
        int y = __shfl_up_sync(0xffffffffu, x, o);
        if (lane >= o) x += y;
    }
    if (lane == 31) ws[w] = x;
    __syncthreads();
    if (t < 32) {
        int y = ws[t];
        #pragma unroll
        for (int o = 1; o < 32; o <<= 1) {
            int z = __shfl_up_sync(0xffffffffu, y, o);
            if (t >= o) y += z;
        }
        ws[t] = y;
    }
    __syncthreads();
    int excl = x - v + (w ? ws[w - 1] : 0);
    if (i < N_NODES) g_rowoff[i] = excl;
    if (t == 1023) g_bsumd[b] = excl + v;
}

__global__ void k_dscan2() {
    __shared__ int ws[4];
    int t = threadIdx.x;            // 128 threads
    if (t == 0) {                   // fused tiny relation scan
        int ro = 0, wo = 0;
        for (int r = 0; r < 8; r++) {
            int c = g_relcnt[r];
            g_roff[r] = ro; g_relcur[r] = ro; g_woff[r] = wo;
            ro += c; wo += (c + 15) / 16;
        }
        g_roff[8] = ro; g_woff[8] = wo;
    }
    int v = (t < NB_D) ? g_bsumd[t] : 0;
    int lane = t & 31, w = t >> 5;
    int x = v;
    #pragma unroll
    for (int o = 1; o < 32; o <<= 1) {
        int y = __shfl_up_sync(0xffffffffu, x, o);
        if (lane >= o) x += y;
    }
    if (lane == 31) ws[w] = x;
    __syncthreads();
    if (t < 4) {
        int y = ws[t];
        for (int o = 1; o < 4; o <<= 1) {
            int z = __shfl_up_sync(0x0000000fu, y, o);
            if (t >= o) y += z;
        }
        ws[t] = y;
    }
    __syncthreads();
    int excl = x - v + (w ? ws[w - 1] : 0);
    if (t < NB_D) g_bsumd[t] = excl;
}

__global__ void k_dscan3() {
    int t = threadIdx.x, b = blockIdx.x;
    int i = b * 1024 + t;
    if (i < N_NODES) {
        int v = g_rowoff[i] + g_bsumd[b];
        g_rowoff[i] = v;
        g_dstcur[i] = v;
    }
    if (i == 0) g_rowoff[N_NODES] = N_EDGES;
}

// ---------------- kernel: fused scatter (relation + dst) --------------------
__global__ void k_scatter(const void* __restrict__ rtp, const void* __restrict__ dstp) {
    __shared__ int cnt[8], base[8];
    int tid = threadIdx.x;
    if (tid < 8) cnt[tid] = 0;
    __syncthreads();
    const int is32 = g_idx32;
    int b0 = blockIdx.x * EPB_HIST;
    int rloc[4];
    #pragma unroll
    for (int c = 0; c < 4; c++) {
        int e = b0 + c * 256 + tid;
        rloc[c] = -1;
        if (e < N_EDGES) {
            rloc[c] = (int)ldidx(rtp, e, is32);
            atomicAdd(&cnt[rloc[c]], 1);
            int d = (int)ldidx(dstp, e, is32);
            int pos = atomicAdd(&g_dstcur[d], 1);
            g_edst[pos] = e;
        }
    }
    __syncthreads();
    if (tid < 8) { base[tid] = atomicAdd(&g_relcur[tid], cnt[tid]); cnt[tid] = 0; }
    __syncthreads();
    #pragma unroll
    for (int c = 0; c < 4; c++) {
        if (rloc[c] >= 0) {
            int pos = base[rloc[c]] + atomicAdd(&cnt[rloc[c]], 1);
            g_eorder[pos] = b0 + c * 256 + tid;
        }
    }
}

// ---------------- kernel: mma.sync bf16 score -------------------------------
// SMEM (dynamic):
//   Wp0  [4096] u32 frag-packed Wsrc  : 0     .. 16384
//   Wp1  [4096] u32 frag-packed Wqual : 16384 .. 32768
//   A    [8 warps][16 rows][36] u32   : 32768 .. 51200
//   bsum [128] f32                    : 51200 .. 51712
//   attnf[128] f32                    : 51712 .. 52224
#define OFF_WP0 0
#define OFF_WP1 16384
#define OFF_A   32768
#define OFF_B   51200
#define OFF_AT  51712
#define SMEM_SCORE_BYTES 52224

extern "C" __global__ void __launch_bounds__(256, 2)
k_score(const float* __restrict__ feat, const float* __restrict__ qual,
        const float* __restrict__ Wsrc, const float* __restrict__ Bsrc,
        const float* __restrict__ Wqual, const float* __restrict__ Bqual,
        const float* __restrict__ attn,
        const void* __restrict__ srcp, const void* __restrict__ nidp)
{
    extern __shared__ unsigned char sm[];
    u32*   wp0   = (u32*)(sm + OFF_WP0);
    u32*   wp1   = (u32*)(sm + OFF_WP1);
    float* bsum  = (float*)(sm + OFF_B);
    float* attnf = (float*)(sm + OFF_AT);

    const int tid = threadIdx.x;
    const int wid = tid >> 5, lane = tid & 31;
    const int g = lane >> 2, tg = lane & 3;
    const int is32 = g_idx32;

    u32* As = (u32*)(sm + OFF_A) + wid * (16 * 36);

    int woff[9], roff[9];
    #pragma unroll
    for (int i = 0; i < 9; i++) { woff[i] = g_woff[i]; roff[i] = g_roff[i]; }
    const int totalw = woff[8];
    const int wtpb = (totalw + gridDim.x - 1) / gridDim.x;
    const int wt0 = blockIdx.x * wtpb;
    const int wt1 = min(wt0 + wtpb, totalw);
    if (wt0 >= wt1) return;

    for (int r = 0; r < 8; r++) {
        const int lo = max(wt0, woff[r]);
        const int hi = min(wt1, woff[r + 1]);
        if (lo >= hi) continue;

        // ---- pack weights for relation r: bf16 fragment-major ----
        __syncthreads();
        for (int idx = tid; idx < 4096; idx += 256) {
            int half = idx & 1;
            int ln   = (idx >> 1) & 31;
            int nt   = (idx >> 6) & 15;
            int ks   = idx >> 10;
            int k = 16 * ks + 2 * (ln & 3) + 8 * half;
            int n = 8 * nt + (ln >> 2);
            const float* w0 = &Wsrc [(r * 64 + k) * 128 + n];
            const float* w1 = &Wqual[(r * 64 + k) * 128 + n];
            wp0[idx] = bf2(w0[0], w0[128]);
            wp1[idx] = bf2(w1[0], w1[128]);
        }
        if (tid < 128) {
            bsum[tid]  = Bsrc[r * 128 + tid] + Bqual[r * 128 + tid];
            attnf[tid] = attn[r * 128 + tid];
        }
        __syncthreads();

        const int relend = roff[r + 1];

        for (int wt = lo + wid; wt < hi; wt += 8) {
            const int estart = roff[r] + (wt - woff[r]) * 16;

            float d[16][4];
            #pragma unroll
            for (int nt = 0; nt < 16; nt++)
                #pragma unroll
                for (int j = 0; j < 4; j++) d[nt][j] = 0.f;

            #pragma unroll
            for (int mat = 0; mat < 2; mat++) {
                // ---- gather 16 rows -> bf16 slab (stride 36 u32) ----
                {
                    int i = lane >> 1, h = lane & 1;
                    int pos = min(estart + i, relend - 1);
                    int e = g_eorder[pos];
                    long long nd = mat == 0 ? ldidx(srcp, e, is32)
                                            : ldidx(nidp, e, is32);
                    const float4* rp = (const float4*)((mat == 0 ? feat : qual)
                                                       + nd * 64) + h * 8;
                    #pragma unroll
                    for (int j = 0; j < 8; j++) {
                        float4 v = rp[j];
                        uint2 t;
                        t.x = bf2(v.x, v.y);
                        t.y = bf2(v.z, v.w);
                        *(uint2*)(As + i * 36 + h * 16 + j * 2) = t;
                    }
                }
                __syncwarp();

                // ---- 4 k-steps x 16 n-tiles ----
                const uint2* wp = (const uint2*)(mat == 0 ? wp0 : wp1);
                #pragma unroll
                for (int ks = 0; ks < 4; ks++) {
                    int c0 = ks * 8 + tg;
                    u32 a0 = As[g * 36 + c0];
                    u32 a1 = As[(g + 8) * 36 + c0];
                    u32 a2 = As[g * 36 + c0 + 4];
                    u32 a3 = As[(g + 8) * 36 + c0 + 4];
                    #pragma unroll
                    for (int nt = 0; nt < 16; nt++) {
                        uint2 b = wp[(ks * 16 + nt) * 32 + lane];
                        mma16(d[nt], a0, a1, a2, a3, b.x, b.y);
                    }
                }
                __syncwarp();
            }

            // ---- epilogue: bias, lrelu, attn-dot, quad reduce, exp ----
            float slo[4] = {0.f, 0.f, 0.f, 0.f};
            float shi[4] = {0.f, 0.f, 0.f, 0.f};
            #pragma unroll
            for (int nt = 0; nt < 16; nt++) {
                int h = nt >> 2;
                int c = 8 * nt + 2 * tg;
                float b0 = bsum[c], b1 = bsum[c + 1];
                float a0 = attnf[c], a1 = attnf[c + 1];
                slo[h] += lrelu(d[nt][0] + b0) * a0 + lrelu(d[nt][1] + b1) * a1;
                shi[h] += lrelu(d[nt][2] + b0) * a0 + lrelu(d[nt][3] + b1) * a1;
            }
            #pragma unroll
            for (int off = 1; off <= 2; off <<= 1) {
                #pragma unroll
                for (int h = 0; h < 4; h++) {
                    slo[h] += __shfl_xor_sync(0xffffffffu, slo[h], off);
                    shi[h] += __shfl_xor_sync(0xffffffffu, shi[h], off);
                }
            }
            if (tg == 0) {
                int plo = estart + g;
                if (plo < relend) {
                    int e = g_eorder[plo];
                    *(float4*)&g_p[e * 4] = make_float4(expf(slo[0]), expf(slo[1]),
                                                        expf(slo[2]), expf(slo[3]));
                }
                int phi = estart + g + 8;
                if (phi < relend) {
                    int e = g_eorder[phi];
                    *(float4*)&g_p[e * 4] = make_float4(expf(shi[0]), expf(shi[1]),
                                                        expf(shi[2]), expf(shi[3]));
                }
            }
        }
    }
}

// ---------------- kernel: per-node CSR aggregation --------------------------
extern "C" __global__ void __launch_bounds__(256)
k_agg(const float* __restrict__ feat, const void* __restrict__ srcp,
      float* __restrict__ out)
{
    const int n = (blockIdx.x * 256 + threadIdx.x) >> 5;   // node id
    const int lane = threadIdx.x & 31;
    if (n >= N_NODES) return;
    const int is32 = g_idx32;

    const int beg = g_rowoff[n], end = g_rowoff[n + 1];

    float a00 = 0.f, a01 = 0.f, a10 = 0.f, a11 = 0.f;
    float a20 = 0.f, a21 = 0.f, a30 = 0.f, a31 = 0.f;
    float d0 = 0.f, d1 = 0.f, d2 = 0.f, d3 = 0.f;

    int e  = (beg < end) ? g_edst[beg] : 0;
    long long s = (beg < end) ? ldidx(srcp, e, is32) : 0;
    for (int i = beg; i < end; i++) {
        int e_n = (i + 1 < end) ? g_edst[i + 1] : 0;
        float4 p  = *(const float4*)&g_p[e * 4];
        float2 f  = *(const float2*)&feat[s * 64 + 2 * lane];
        long long s_n = (i + 1 < end) ? ldidx(srcp, e_n, is32) : 0;
        a00 += p.x * f.x; a01 += p.x * f.y; d0 += p.x;
        a10 += p.y * f.x; a11 += p.y * f.y; d1 += p.y;
        a20 += p.z * f.x; a21 += p.z * f.y; d2 += p.z;
        a30 += p.w * f.x; a31 += p.w * f.y; d3 += p.w;
        e = e_n; s = s_n;
    }

    float i0 = d0 > 0.f ? __frcp_rn(d0) : 0.f;
    float i1 = d1 > 0.f ? __frcp_rn(d1) : 0.f;
    float i2 = d2 > 0.f ? __frcp_rn(d2) : 0.f;
    float i3 = d3 > 0.f ? __frcp_rn(d3) : 0.f;

    float* o = out + (size_t)n * 256 + 2 * lane;
    *(float2*)(o)       = make_float2(a00 * i0, a01 * i0);
    *(float2*)(o + 64)  = make_float2(a10 * i1, a11 * i1);
    *(float2*)(o + 128) = make_float2(a20 * i2, a21 * i2);
    *(float2*)(o + 192) = make_float2(a30 * i3, a31 * i3);
}

// ---------------- launcher --------------------------------------------------
extern "C" void kernel_launch(void* const* d_in, const int* in_sizes, int n_in,
                              void* d_out, int out_size)
{
    const float* feat  = (const float*)d_in[0];
    const float* qual  = (const float*)d_in[1];
    const float* Wsrc  = (const float*)d_in[2];
    const float* Bsrc  = (const float*)d_in[3];
    const float* Wqual = (const float*)d_in[4];
    const float* Bqual = (const float*)d_in[5];
    const float* attn  = (const float*)d_in[6];
    const void*  src   = d_in[7];
    const void*  dst   = d_in[8];
    const void*  rt    = d_in[9];
    const void*  nid   = d_in[10];
    float* out = (float*)d_out;

    static bool attr_set = false;
    if (!attr_set) {
        cudaFuncSetAttribute(k_score, cudaFuncAttributeMaxDynamicSharedMemorySize,
                             SMEM_SCORE_BYTES);
        attr_set = true;
    }

    k_zinit<<<(N_NODES + 255) / 256, 256>>>(src);
    k_hist<<<NBLK_HIST, 256>>>(rt, dst);
    k_dscan1<<<NB_D, 1024>>>();
    k_dscan2<<<1, 128>>>();
    k_dscan3<<<NB_D, 1024>>>();
    k_scatter<<<NBLK_HIST, 256>>>(rt, dst);

    k_score<<<296, 256, SMEM_SCORE_BYTES>>>(feat, qual, Wsrc, Bsrc, Wqual, Bqual,
                                            attn, src, nid);

    k_agg<<<(N_NODES * 32 + 255) / 256, 256>>>(feat, src, out);
}

// round 6
// speedup vs baseline: 1.1676x; 1.1676x over previous
#include <cuda_runtime.h>
#include <cstdint>

#define N_NODES   100000
#define N_REL     8
#define IN_FEATS  64
#define HD        128
#define N_EDGES   800000
#define NEG_SLOPE 0.2f

#define EPB_HIST  1024
#define NBLK_HIST ((N_EDGES + EPB_HIST - 1) / EPB_HIST)   // 782
#define NB_D      ((N_NODES + 1023) / 1024)               // 98

typedef unsigned long long u64;
typedef unsigned int u32;

// ---------------- scratch ---------------------------------------------------
__device__ float g_p[N_EDGES * 4];
__device__ int   g_eorder[N_EDGES];      // edges sorted by relation
__device__ int   g_edst[N_EDGES];        // edges sorted by dst
__device__ int   g_relcnt[8];            // zero-init; re-zeroed by k_scan
__device__ int   g_relcur[8];
__device__ int   g_roff[9];
__device__ int   g_woff[9];
__device__ int   g_dstcnt[N_NODES];      // zero-init; re-zeroed by k_agg
__device__ int   g_rowoff[N_NODES + 1];
__device__ int   g_dstcur[N_NODES];
__device__ int   g_agg_v[NB_D];
__device__ int   g_agg_f[NB_D];          // zero-init; re-zeroed by k_agg

// ---------------- helpers ---------------------------------------------------
__device__ __forceinline__ long long ldidx(const void* p, int i, int is32) {
    return is32 ? (long long)((const int*)p)[i] : ((const long long*)p)[i];
}
__device__ __forceinline__ float lrelu(float v) { return v > 0.0f ? v : NEG_SLOPE * v; }
__device__ __forceinline__ u32 tf32(float f) {
    u32 r; asm("cvt.rna.tf32.f32 %0, %1;" : "=r"(r) : "f"(f)); return r;
}
__device__ __forceinline__ void mma8(float* d, u32 a0, u32 a1, u32 a2, u32 a3,
                                     u32 b0, u32 b1) {
    asm volatile(
        "mma.sync.aligned.m16n8k8.row.col.f32.tf32.tf32.f32 "
        "{%0,%1,%2,%3}, {%4,%5,%6,%7}, {%8,%9}, {%0,%1,%2,%3};"
        : "+f"(d[0]), "+f"(d[1]), "+f"(d[2]), "+f"(d[3])
        : "r"(a0), "r"(a1), "r"(a2), "r"(a3), "r"(b0), "r"(b1));
}
// detect int32-vs-int64 index encoding from a node-id array (values < N_NODES).
// If data were int32, the high halves of these 16 words are 16 random node ids;
// all-zero has probability ~1e-80 -> robust.
__device__ __forceinline__ int detect32(const void* p) {
    const long long* q = (const long long*)p;
    int bad = 0;
    #pragma unroll
    for (int j = 0; j < 16; j++) {
        long long v = q[j];
        if (v < 0 || v >= N_NODES) bad = 1;
    }
    return bad;
}

// ---------------- kernel 1: fused histogram (relation + dst) ----------------
__global__ void k_hist(const void* __restrict__ rtp, const void* __restrict__ dstp) {
    __shared__ int cnt[8];
    __shared__ int s_is32;
    int tid = threadIdx.x;
    if (tid < 8) cnt[tid] = 0;
    if (tid == 0) s_is32 = detect32(dstp);
    __syncthreads();
    const int is32 = s_is32;
    int base = blockIdx.x * EPB_HIST;
    for (int i = tid; i < EPB_HIST; i += 256) {
        int e = base + i;
        if (e < N_EDGES) {
            atomicAdd(&cnt[(int)ldidx(rtp, e, is32)], 1);
            atomicAdd(&g_dstcnt[(int)ldidx(dstp, e, is32)], 1);
        }
    }
    __syncthreads();
    if (tid < 8) atomicAdd(&g_relcnt[tid], cnt[tid]);
}

// ---------------- kernel 2: single-launch dst scan (decoupled lookback) -----
// 98 blocks, all co-resident on 148 SMs -> lookback spin cannot deadlock.
// Block 0 also performs the 8-entry relation scan and re-zeros g_relcnt.
__global__ void __launch_bounds__(1024) k_scan() {
    __shared__ int ws[32];
    __shared__ int s_pred;
    int t = threadIdx.x, b = blockIdx.x;
    int i = b * 1024 + t;
    int v = (i < N_NODES) ? g_dstcnt[i] : 0;
    int lane = t & 31, w = t >> 5;
    int x = v;
    #pragma unroll
    for (int o = 1; o < 32; o <<= 1) {
        int y = __shfl_up_sync(0xffffffffu, x, o);
        if (lane >= o) x += y;
    }
    if (lane == 31) ws[w] = x;
    __syncthreads();
    if (t < 32) {
        int y = ws[t];
        #pragma unroll
        for (int o = 1; o < 32; o <<= 1) {
            int z = __shfl_up_sync(0xffffffffu, y, o);
            if (t >= o) y += z;
        }
        ws[t] = y;
    }
    __syncthreads();
    int excl = x - v + (w ? ws[w - 1] : 0);
    int btot = ws[31];
    if (t == 0) {
        s_pred = 0;
        g_agg_v[b] = btot;
        __threadfence();
        atomicExch(&g_agg_f[b], 1);
    }
    __syncthreads();
    if (t < b) {
        while (atomicAdd(&g_agg_f[t], 0) == 0) {}
        atomicAdd(&s_pred, atomicAdd(&g_agg_v[t], 0));
    }
    __syncthreads();
    int base = s_pred;
    if (i < N_NODES) {
        int val = base + excl;
        g_rowoff[i] = val;
        g_dstcur[i] = val;
    }
    if (b == 0 && t == 0) {
        int ro = 0, wo = 0;
        for (int r = 0; r < 8; r++) {
            int c = g_relcnt[r];
            g_roff[r] = ro; g_relcur[r] = ro; g_woff[r] = wo;
            ro += c; wo += (c + 15) / 16;
            g_relcnt[r] = 0;               // ready for next replay
        }
        g_roff[8] = ro; g_woff[8] = wo;
        g_rowoff[N_NODES] = N_EDGES;
    }
}

// ---------------- kernel 3: fused scatter (relation + dst) ------------------
__global__ void k_scatter(const void* __restrict__ rtp, const void* __restrict__ dstp) {
    __shared__ int cnt[8], base[8];
    __shared__ int s_is32;
    int tid = threadIdx.x;
    if (tid < 8) cnt[tid] = 0;
    if (tid == 0) s_is32 = detect32(dstp);
    __syncthreads();
    const int is32 = s_is32;
    int b0 = blockIdx.x * EPB_HIST;
    int rloc[4];
    #pragma unroll
    for (int c = 0; c < 4; c++) {
        int e = b0 + c * 256 + tid;
        rloc[c] = -1;
        if (e < N_EDGES) {
            rloc[c] = (int)ldidx(rtp, e, is32);
            atomicAdd(&cnt[rloc[c]], 1);
            int d = (int)ldidx(dstp, e, is32);
            int pos = atomicAdd(&g_dstcur[d], 1);
            g_edst[pos] = e;
        }
    }
    __syncthreads();
    if (tid < 8) { base[tid] = atomicAdd(&g_relcur[tid], cnt[tid]); cnt[tid] = 0; }
    __syncthreads();
    #pragma unroll
    for (int c = 0; c < 4; c++) {
        if (rloc[c] >= 0) {
            int pos = base[rloc[c]] + atomicAdd(&cnt[rloc[c]], 1);
            g_eorder[pos] = b0 + c * 256 + tid;
        }
    }
}

// ---------------- kernel 4: mma.sync tf32 score (profiled slot) -------------
// SMEM (dynamic):
//   Wp0  [8192] u32 frag-packed Wsrc  : 0      .. 32768
//   Wp1  [8192] u32 frag-packed Wqual : 32768  .. 65536
//   A    [8 warps][16 rows][68] u32   : 65536  .. 100352
//   bsum [128] f32                    : 100352 .. 100864
//   attnf[128] f32                    : 100864 .. 101376
#define OFF_WP0 0
#define OFF_WP1 32768
#define OFF_A   65536
#define OFF_B   100352
#define OFF_AT  100864
#define SMEM_SCORE_BYTES 101376

extern "C" __global__ void __launch_bounds__(256, 2)
k_score(const float* __restrict__ feat, const float* __restrict__ qual,
        const float* __restrict__ Wsrc, const float* __restrict__ Bsrc,
        const float* __restrict__ Wqual, const float* __restrict__ Bqual,
        const float* __restrict__ attn,
        const void* __restrict__ srcp, const void* __restrict__ nidp)
{
    extern __shared__ unsigned char sm[];
    u32*   wp0   = (u32*)(sm + OFF_WP0);
    u32*   wp1   = (u32*)(sm + OFF_WP1);
    float* bsum  = (float*)(sm + OFF_B);
    float* attnf = (float*)(sm + OFF_AT);
    __shared__ int s_is32;

    const int tid = threadIdx.x;
    const int wid = tid >> 5, lane = tid & 31;
    const int g = lane >> 2, tg = lane & 3;

    if (tid == 0) s_is32 = detect32(srcp);
    __syncthreads();
    const int is32 = s_is32;

    u32* As = (u32*)(sm + OFF_A) + wid * (16 * 68);

    int woff[9], roff[9];
    #pragma unroll
    for (int i = 0; i < 9; i++) { woff[i] = g_woff[i]; roff[i] = g_roff[i]; }
    const int totalw = woff[8];
    const int wtpb = (totalw + gridDim.x - 1) / gridDim.x;
    const int wt0 = blockIdx.x * wtpb;
    const int wt1 = min(wt0 + wtpb, totalw);
    if (wt0 >= wt1) return;

    for (int r = 0; r < 8; r++) {
        const int lo = max(wt0, woff[r]);
        const int hi = min(wt1, woff[r + 1]);
        if (lo >= hi) continue;

        // ---- pack weights for relation r into fragment-major SMEM ----
        __syncthreads();
        for (int idx = tid; idx < 8192; idx += 256) {
            int w  = idx & 3;
            int ln = (idx >> 2) & 31;
            int nt = (idx >> 7) & 15;
            int k4 = idx >> 11;
            int k  = 16 * k4 + (ln & 3) + 4 * w;
            int n  = 8 * nt + (ln >> 2);
            wp0[idx] = tf32(Wsrc [(r * 64 + k) * 128 + n]);
            wp1[idx] = tf32(Wqual[(r * 64 + k) * 128 + n]);
        }
        if (tid < 128) {
            bsum[tid]  = Bsrc[r * 128 + tid] + Bqual[r * 128 + tid];
            attnf[tid] = attn[r * 128 + tid];
        }
        __syncthreads();

        const int relend = roff[r + 1];

        for (int wt = lo + wid; wt < hi; wt += 8) {
            const int estart = roff[r] + (wt - woff[r]) * 16;

            float d[16][4];
            #pragma unroll
            for (int nt = 0; nt < 16; nt++)
                #pragma unroll
                for (int j = 0; j < 4; j++) d[nt][j] = 0.f;

            #pragma unroll
            for (int mat = 0; mat < 2; mat++) {
                // ---- gather 16 rows into warp-private slab ----
                {
                    int i = lane >> 1, h = lane & 1;
                    int pos = min(estart + i, relend - 1);
                    int e = g_eorder[pos];
                    long long nd = mat == 0 ? ldidx(srcp, e, is32)
                                            : ldidx(nidp, e, is32);
                    const float4* rp = (const float4*)((mat == 0 ? feat : qual)
                                                       + nd * 64) + h * 8;
                    #pragma unroll
                    for (int j = 0; j < 8; j++) {
                        float4 v = rp[j];
                        uint4 t;
                        t.x = tf32(v.x); t.y = tf32(v.y);
                        t.z = tf32(v.z); t.w = tf32(v.w);
                        *(uint4*)(As + i * 68 + h * 32 + j * 4) = t;
                    }
                }
                __syncwarp();

                // ---- 8 k-steps x 16 n-tiles ----
                const uint4* wp = (const uint4*)(mat == 0 ? wp0 : wp1);
                #pragma unroll
                for (int k4 = 0; k4 < 4; k4++) {
                    int c0 = 16 * k4 + tg;
                    u32 a00 = As[g * 68 + c0];
                    u32 a01 = As[(g + 8) * 68 + c0];
                    u32 a02 = As[g * 68 + c0 + 4];
                    u32 a03 = As[(g + 8) * 68 + c0 + 4];
                    u32 a10 = As[g * 68 + c0 + 8];
                    u32 a11 = As[(g + 8) * 68 + c0 + 8];
                    u32 a12 = As[g * 68 + c0 + 12];
                    u32 a13 = As[(g + 8) * 68 + c0 + 12];
                    #pragma unroll
                    for (int nt = 0; nt < 16; nt++) {
                        uint4 b = wp[(k4 * 16 + nt) * 32 + lane];
                        mma8(d[nt], a00, a01, a02, a03, b.x, b.y);
                        mma8(d[nt], a10, a11, a12, a13, b.z, b.w);
                    }
                }
                __syncwarp();
            }

            // ---- epilogue: bias, lrelu, attn-dot, quad reduce, exp ----
            float slo[4] = {0.f, 0.f, 0.f, 0.f};
            float shi[4] = {0.f, 0.f, 0.f, 0.f};
            #pragma unroll
            for (int nt = 0; nt < 16; nt++) {
                int h = nt >> 2;
                int c = 8 * nt + 2 * tg;
                float b0 = bsum[c], b1 = bsum[c + 1];
                float a0 = attnf[c], a1 = attnf[c + 1];
                slo[h] += lrelu(d[nt][0] + b0) * a0 + lrelu(d[nt][1] + b1) * a1;
                shi[h] += lrelu(d[nt][2] + b0) * a0 + lrelu(d[nt][3] + b1) * a1;
            }
            #pragma unroll
            for (int off = 1; off <= 2; off <<= 1) {
                #pragma unroll
                for (int h = 0; h < 4; h++) {
                    slo[h] += __shfl_xor_sync(0xffffffffu, slo[h], off);
                    shi[h] += __shfl_xor_sync(0xffffffffu, shi[h], off);
                }
            }
            if (tg == 0) {
                int plo = estart + g;
                if (plo < relend) {
                    int e = g_eorder[plo];
                    *(float4*)&g_p[e * 4] = make_float4(expf(slo[0]), expf(slo[1]),
                                                        expf(slo[2]), expf(slo[3]));
                }
                int phi = estart + g + 8;
                if (phi < relend) {
                    int e = g_eorder[phi];
                    *(float4*)&g_p[e * 4] = make_float4(expf(shi[0]), expf(shi[1]),
                                                        expf(shi[2]), expf(shi[3]));
                }
            }
        }
    }
}

// ---------------- kernel 5: per-node CSR aggregation + counter cleanup ------
extern "C" __global__ void __launch_bounds__(256)
k_agg(const float* __restrict__ feat, const void* __restrict__ srcp,
      float* __restrict__ out)
{
    __shared__ int s_is32;
    const int gid = blockIdx.x * 256 + threadIdx.x;
    if (threadIdx.x == 0) s_is32 = detect32(srcp);
    if (gid < NB_D) g_agg_f[gid] = 0;           // reset scan flags for next replay
    __syncthreads();
    const int is32 = s_is32;

    const int n = gid >> 5;                      // node id (warp per node)
    const int lane = threadIdx.x & 31;
    if (n >= N_NODES) return;
    if (lane == 0) g_dstcnt[n] = 0;              // reset histogram for next replay

    const int beg = g_rowoff[n], end = g_rowoff[n + 1];

    float a00 = 0.f, a01 = 0.f, a10 = 0.f, a11 = 0.f;
    float a20 = 0.f, a21 = 0.f, a30 = 0.f, a31 = 0.f;
    float d0 = 0.f, d1 = 0.f, d2 = 0.f, d3 = 0.f;

    int e  = (beg < end) ? g_edst[beg] : 0;
    long long s = (beg < end) ? ldidx(srcp, e, is32) : 0;
    for (int i = beg; i < end; i++) {
        int e_n = (i + 1 < end) ? g_edst[i + 1] : 0;
        float4 p  = *(const float4*)&g_p[e * 4];
        float2 f  = *(const float2*)&feat[s * 64 + 2 * lane];
        long long s_n = (i + 1 < end) ? ldidx(srcp, e_n, is32) : 0;
        a00 += p.x * f.x; a01 += p.x * f.y; d0 += p.x;
        a10 += p.y * f.x; a11 += p.y * f.y; d1 += p.y;
        a20 += p.z * f.x; a21 += p.z * f.y; d2 += p.z;
        a30 += p.w * f.x; a31 += p.w * f.y; d3 += p.w;
        e = e_n; s = s_n;
    }

    float i0 = d0 > 0.f ? __frcp_rn(d0) : 0.f;
    float i1 = d1 > 0.f ? __frcp_rn(d1) : 0.f;
    float i2 = d2 > 0.f ? __frcp_rn(d2) : 0.f;
    float i3 = d3 > 0.f ? __frcp_rn(d3) : 0.f;

    float* o = out + (size_t)n * 256 + 2 * lane;
    *(float2*)(o)       = make_float2(a00 * i0, a01 * i0);
    *(float2*)(o + 64)  = make_float2(a10 * i1, a11 * i1);
    *(float2*)(o + 128) = make_float2(a20 * i2, a21 * i2);
    *(float2*)(o + 192) = make_float2(a30 * i3, a31 * i3);
}

// ---------------- launcher --------------------------------------------------
extern "C" void kernel_launch(void* const* d_in, const int* in_sizes, int n_in,
                              void* d_out, int out_size)
{
    const float* feat  = (const float*)d_in[0];
    const float* qual  = (const float*)d_in[1];
    const float* Wsrc  = (const float*)d_in[2];
    const float* Bsrc  = (const float*)d_in[3];
    const float* Wqual = (const float*)d_in[4];
    const float* Bqual = (const float*)d_in[5];
    const float* attn  = (const float*)d_in[6];
    const void*  src   = d_in[7];
    const void*  dst   = d_in[8];
    const void*  rt    = d_in[9];
    const void*  nid   = d_in[10];
    float* out = (float*)d_out;

    static bool attr_set = false;
    if (!attr_set) {
        cudaFuncSetAttribute(k_score, cudaFuncAttributeMaxDynamicSharedMemorySize,
                             SMEM_SCORE_BYTES);
        attr_set = true;
    }

    k_hist<<<NBLK_HIST, 256>>>(rt, dst);                    // #1
    k_scan<<<NB_D, 1024>>>();                               // #2
    k_scatter<<<NBLK_HIST, 256>>>(rt, dst);                 // #3
    k_score<<<296, 256, SMEM_SCORE_BYTES>>>(feat, qual,     // #4 <- profiled
                                            Wsrc, Bsrc, Wqual, Bqual,
                                            attn, src, nid);
    k_agg<<<(N_NODES * 32 + 255) / 256, 256>>>(feat, src, out);  // #5
}

// round 7
// speedup vs baseline: 1.2252x; 1.0493x over previous
#include <cuda_runtime.h>
#include <cstdint>

#define N_NODES   100000
#define N_REL     8
#define IN_FEATS  64
#define HD        128
#define N_EDGES   800000
#define NEG_SLOPE 0.2f

#define EPB_HIST  1024
#define NBLK_HIST ((N_EDGES + EPB_HIST - 1) / EPB_HIST)   // 782
#define NB_D      ((N_NODES + 1023) / 1024)               // 98

typedef unsigned long long u64;
typedef unsigned int u32;

// ---------------- scratch ---------------------------------------------------
__device__ float g_p[N_EDGES * 4];
__device__ int   g_eorder[N_EDGES];      // edges sorted by relation
__device__ int   g_edst[N_EDGES];        // edges sorted by dst
__device__ int   g_relcnt[8];            // zero-init; re-zeroed by k_scan
__device__ int   g_relcur[8];
__device__ int   g_roff[9];
__device__ int   g_woff[9];              // 32-edge tile offsets per relation
__device__ int   g_dstcnt[N_NODES];      // zero-init; re-zeroed by k_agg
__device__ int   g_rowoff[N_NODES + 1];
__device__ int   g_dstcur[N_NODES];
__device__ int   g_agg_v[NB_D];
__device__ int   g_agg_f[NB_D];          // zero-init; re-zeroed by k_agg

// ---------------- helpers ---------------------------------------------------
__device__ __forceinline__ long long ldidx(const void* p, int i, int is32) {
    return is32 ? (long long)((const int*)p)[i] : ((const long long*)p)[i];
}
__device__ __forceinline__ float lrelu(float v) { return v > 0.0f ? v : NEG_SLOPE * v; }
__device__ __forceinline__ u32 tf32(float f) {
    u32 r; asm("cvt.rna.tf32.f32 %0, %1;" : "=r"(r) : "f"(f)); return r;
}
__device__ __forceinline__ void mma8(float* d, u32 a0, u32 a1, u32 a2, u32 a3,
                                     u32 b0, u32 b1) {
    asm volatile(
        "mma.sync.aligned.m16n8k8.row.col.f32.tf32.tf32.f32 "
        "{%0,%1,%2,%3}, {%4,%5,%6,%7}, {%8,%9}, {%0,%1,%2,%3};"
        : "+f"(d[0]), "+f"(d[1]), "+f"(d[2]), "+f"(d[3])
        : "r"(a0), "r"(a1), "r"(a2), "r"(a3), "r"(b0), "r"(b1));
}
__device__ __forceinline__ void barpair(int id) {
    asm volatile("bar.sync %0, 64;" :: "r"(id) : "memory");
}
__device__ __forceinline__ int detect32(const void* p) {
    const long long* q = (const long long*)p;
    int bad = 0;
    #pragma unroll
    for (int j = 0; j < 16; j++) {
        long long v = q[j];
        if (v < 0 || v >= N_NODES) bad = 1;
    }
    return bad;
}

// ---------------- kernel 1: fused histogram (relation + dst) ----------------
__global__ void k_hist(const void* __restrict__ rtp, const void* __restrict__ dstp) {
    __shared__ int cnt[8];
    __shared__ int s_is32;
    int tid = threadIdx.x;
    if (tid < 8) cnt[tid] = 0;
    if (tid == 0) s_is32 = detect32(dstp);
    __syncthreads();
    const int is32 = s_is32;
    int base = blockIdx.x * EPB_HIST;
    for (int i = tid; i < EPB_HIST; i += 256) {
        int e = base + i;
        if (e < N_EDGES) {
            atomicAdd(&cnt[(int)ldidx(rtp, e, is32)], 1);
            atomicAdd(&g_dstcnt[(int)ldidx(dstp, e, is32)], 1);
        }
    }
    __syncthreads();
    if (tid < 8) atomicAdd(&g_relcnt[tid], cnt[tid]);
}

// ---------------- kernel 2: single-launch dst scan (decoupled lookback) -----
__global__ void __launch_bounds__(1024) k_scan() {
    __shared__ int ws[32];
    __shared__ int s_pred;
    int t = threadIdx.x, b = blockIdx.x;
    int i = b * 1024 + t;
    int v = (i < N_NODES) ? g_dstcnt[i] : 0;
    int lane = t & 31, w = t >> 5;
    int x = v;
    #pragma unroll
    for (int o = 1; o < 32; o <<= 1) {
        int y = __shfl_up_sync(0xffffffffu, x, o);
        if (lane >= o) x += y;
    }
    if (lane == 31) ws[w] = x;
    __syncthreads();
    if (t < 32) {
        int y = ws[t];
        #pragma unroll
        for (int o = 1; o < 32; o <<= 1) {
            int z = __shfl_up_sync(0xffffffffu, y, o);
            if (t >= o) y += z;
        }
        ws[t] = y;
    }
    __syncthreads();
    int excl = x - v + (w ? ws[w - 1] : 0);
    int btot = ws[31];
    if (t == 0) {
        s_pred = 0;
        g_agg_v[b] = btot;
        __threadfence();
        atomicExch(&g_agg_f[b], 1);
    }
    __syncthreads();
    if (t < b) {
        while (atomicAdd(&g_agg_f[t], 0) == 0) {}
        atomicAdd(&s_pred, atomicAdd(&g_agg_v[t], 0));
    }
    __syncthreads();
    int base = s_pred;
    if (i < N_NODES) {
        int val = base + excl;
        g_rowoff[i] = val;
        g_dstcur[i] = val;
    }
    if (b == 0 && t == 0) {
        int ro = 0, wo = 0;
        for (int r = 0; r < 8; r++) {
            int c = g_relcnt[r];
            g_roff[r] = ro; g_relcur[r] = ro; g_woff[r] = wo;
            ro += c; wo += (c + 31) / 32;          // 32-edge tiles
            g_relcnt[r] = 0;
        }
        g_roff[8] = ro; g_woff[8] = wo;
        g_rowoff[N_NODES] = N_EDGES;
    }
}

// ---------------- kernel 3: fused scatter (relation + dst) ------------------
__global__ void k_scatter(const void* __restrict__ rtp, const void* __restrict__ dstp) {
    __shared__ int cnt[8], base[8];
    __shared__ int s_is32;
    int tid = threadIdx.x;
    if (tid < 8) cnt[tid] = 0;
    if (tid == 0) s_is32 = detect32(dstp);
    __syncthreads();
    const int is32 = s_is32;
    int b0 = blockIdx.x * EPB_HIST;
    int rloc[4];
    #pragma unroll
    for (int c = 0; c < 4; c++) {
        int e = b0 + c * 256 + tid;
        rloc[c] = -1;
        if (e < N_EDGES) {
            rloc[c] = (int)ldidx(rtp, e, is32);
            atomicAdd(&cnt[rloc[c]], 1);
            int d = (int)ldidx(dstp, e, is32);
            int pos = atomicAdd(&g_dstcur[d], 1);
            g_edst[pos] = e;
        }
    }
    __syncthreads();
    if (tid < 8) { base[tid] = atomicAdd(&g_relcur[tid], cnt[tid]); cnt[tid] = 0; }
    __syncthreads();
    #pragma unroll
    for (int c = 0; c < 4; c++) {
        if (rloc[c] >= 0) {
            int pos = base[rloc[c]] + atomicAdd(&cnt[rloc[c]], 1);
            g_eorder[pos] = b0 + c * 256 + tid;
        }
    }
}

// ---------------- kernel 4: mma.sync tf32 score, warp-pair tiles ------------
// 2 warps share a 32-edge tile; each warp computes N=64 (its 2 heads) for
// all 32 edges. B-fragment smem reads amortize over 2 m-tiles.
// SMEM (dynamic):
//   Wp0  [8192] u32 frag-packed Wsrc  : 0      .. 32768
//   Wp1  [8192] u32 frag-packed Wqual : 32768  .. 65536
//   A    [4 pairs][32 rows][68] u32   : 65536  .. 100352
//   bsum [128] f32                    : 100352 .. 100864
//   attnf[128] f32                    : 100864 .. 101376
#define OFF_WP0 0
#define OFF_WP1 32768
#define OFF_A   65536
#define OFF_B   100352
#define OFF_AT  100864
#define SMEM_SCORE_BYTES 101376

extern "C" __global__ void __launch_bounds__(256, 2)
k_score(const float* __restrict__ feat, const float* __restrict__ qual,
        const float* __restrict__ Wsrc, const float* __restrict__ Bsrc,
        const float* __restrict__ Wqual, const float* __restrict__ Bqual,
        const float* __restrict__ attn,
        const void* __restrict__ srcp, const void* __restrict__ nidp)
{
    extern __shared__ unsigned char sm[];
    u32*   wp0   = (u32*)(sm + OFF_WP0);
    u32*   wp1   = (u32*)(sm + OFF_WP1);
    float* bsum  = (float*)(sm + OFF_B);
    float* attnf = (float*)(sm + OFF_AT);
    __shared__ int s_is32;

    const int tid   = threadIdx.x;
    const int wid   = tid >> 5, lane = tid & 31;
    const int pair  = wid >> 1;          // 0..3
    const int wpair = wid & 1;           // n-half owned by this warp
    const int ptid  = tid & 63;          // thread id within pair
    const int g = lane >> 2, tg = lane & 3;

    if (tid == 0) s_is32 = detect32(srcp);
    __syncthreads();
    const int is32 = s_is32;

    u32* As = (u32*)(sm + OFF_A) + pair * (32 * 68);

    int woff[9], roff[9];
    #pragma unroll
    for (int i = 0; i < 9; i++) { woff[i] = g_woff[i]; roff[i] = g_roff[i]; }
    const int totalw = woff[8];
    const int wtpb = (totalw + gridDim.x - 1) / gridDim.x;
    const int wt0 = blockIdx.x * wtpb;
    const int wt1 = min(wt0 + wtpb, totalw);
    if (wt0 >= wt1) return;

    for (int r = 0; r < 8; r++) {
        const int lo = max(wt0, woff[r]);
        const int hi = min(wt1, woff[r + 1]);
        if (lo >= hi) continue;

        // ---- pack weights for relation r into fragment-major SMEM ----
        __syncthreads();
        for (int idx = tid; idx < 8192; idx += 256) {
            int w  = idx & 3;
            int ln = (idx >> 2) & 31;
            int nt = (idx >> 7) & 15;
            int k4 = idx >> 11;
            int k  = 16 * k4 + (ln & 3) + 4 * w;
            int n  = 8 * nt + (ln >> 2);
            wp0[idx] = tf32(Wsrc [(r * 64 + k) * 128 + n]);
            wp1[idx] = tf32(Wqual[(r * 64 + k) * 128 + n]);
        }
        if (tid < 128) {
            bsum[tid]  = Bsrc[r * 128 + tid] + Bqual[r * 128 + tid];
            attnf[tid] = attn[r * 128 + tid];
        }
        __syncthreads();

        const int relend = roff[r + 1];

        for (int wt = lo + pair; wt < hi; wt += 4) {
            const int estart = roff[r] + (wt - woff[r]) * 32;

            float d[2][8][4];
            #pragma unroll
            for (int mt = 0; mt < 2; mt++)
                #pragma unroll
                for (int nt = 0; nt < 8; nt++)
                    #pragma unroll
                    for (int j = 0; j < 4; j++) d[mt][nt][j] = 0.f;

            #pragma unroll
            for (int mat = 0; mat < 2; mat++) {
                // ---- both warps gather 32 rows into pair slab ----
                {
                    int row = ptid >> 1, h = ptid & 1;
                    int pos = min(estart + row, relend - 1);
                    int e = g_eorder[pos];
                    long long nd = mat == 0 ? ldidx(srcp, e, is32)
                                            : ldidx(nidp, e, is32);
                    const float4* rp = (const float4*)((mat == 0 ? feat : qual)
                                                       + nd * 64) + h * 8;
                    #pragma unroll
                    for (int j = 0; j < 8; j++) {
                        float4 v = rp[j];
                        uint4 t;
                        t.x = tf32(v.x); t.y = tf32(v.y);
                        t.z = tf32(v.z); t.w = tf32(v.w);
                        *(uint4*)(As + row * 68 + h * 32 + j * 4) = t;
                    }
                }
                barpair(1 + pair);

                // ---- 4 k4-steps x (2 m-tiles x 8 n-tiles) ----
                const uint4* wp = (const uint4*)(mat == 0 ? wp0 : wp1);
                #pragma unroll
                for (int k4 = 0; k4 < 4; k4++) {
                    int c0 = 16 * k4 + tg;
                    u32 a[2][8];
                    #pragma unroll
                    for (int mt = 0; mt < 2; mt++) {
                        int rb = 16 * mt;
                        a[mt][0] = As[(rb + g) * 68 + c0];
                        a[mt][1] = As[(rb + g + 8) * 68 + c0];
                        a[mt][2] = As[(rb + g) * 68 + c0 + 4];
                        a[mt][3] = As[(rb + g + 8) * 68 + c0 + 4];
                        a[mt][4] = As[(rb + g) * 68 + c0 + 8];
                        a[mt][5] = As[(rb + g + 8) * 68 + c0 + 8];
                        a[mt][6] = As[(rb + g) * 68 + c0 + 12];
                        a[mt][7] = As[(rb + g + 8) * 68 + c0 + 12];
                    }
                    #pragma unroll
                    for (int ntl = 0; ntl < 8; ntl++) {
                        int nt = 8 * wpair + ntl;
                        uint4 b = wp[(k4 * 16 + nt) * 32 + lane];
                        #pragma unroll
                        for (int mt = 0; mt < 2; mt++) {
                            mma8(d[mt][ntl], a[mt][0], a[mt][1], a[mt][2], a[mt][3],
                                 b.x, b.y);
                            mma8(d[mt][ntl], a[mt][4], a[mt][5], a[mt][6], a[mt][7],
                                 b.z, b.w);
                        }
                    }
                }
                barpair(1 + pair);   // slab consumed; safe to overwrite
            }

            // ---- epilogue: this warp owns heads {2*wpair, 2*wpair+1} ----
            float slo[2][2] = {{0.f, 0.f}, {0.f, 0.f}};   // [mt][h'] rows g
            float shi[2][2] = {{0.f, 0.f}, {0.f, 0.f}};   // [mt][h'] rows g+8
            #pragma unroll
            for (int ntl = 0; ntl < 8; ntl++) {
                int hp = ntl >> 2;
                int c = 8 * (8 * wpair + ntl) + 2 * tg;
                float b0 = bsum[c], b1 = bsum[c + 1];
                float a0 = attnf[c], a1 = attnf[c + 1];
                #pragma unroll
                for (int mt = 0; mt < 2; mt++) {
                    slo[mt][hp] += lrelu(d[mt][ntl][0] + b0) * a0
                                 + lrelu(d[mt][ntl][1] + b1) * a1;
                    shi[mt][hp] += lrelu(d[mt][ntl][2] + b0) * a0
                                 + lrelu(d[mt][ntl][3] + b1) * a1;
                }
            }
            #pragma unroll
            for (int off = 1; off <= 2; off <<= 1) {
                #pragma unroll
                for (int mt = 0; mt < 2; mt++)
                    #pragma unroll
                    for (int hp = 0; hp < 2; hp++) {
                        slo[mt][hp] += __shfl_xor_sync(0xffffffffu, slo[mt][hp], off);
                        shi[mt][hp] += __shfl_xor_sync(0xffffffffu, shi[mt][hp], off);
                    }
            }
            if (tg == 0) {
                #pragma unroll
                for (int mt = 0; mt < 2; mt++) {
                    int plo = estart + 16 * mt + g;
                    if (plo < relend) {
                        int e = g_eorder[plo];
                        *(float2*)&g_p[e * 4 + 2 * wpair] =
                            make_float2(expf(slo[mt][0]), expf(slo[mt][1]));
                    }
                    int phi = estart + 16 * mt + g + 8;
                    if (phi < relend) {
                        int e = g_eorder[phi];
                        *(float2*)&g_p[e * 4 + 2 * wpair] =
                            make_float2(expf(shi[mt][0]), expf(shi[mt][1]));
                    }
                }
            }
        }
    }
}

// ---------------- kernel 5: per-node CSR aggregation + counter cleanup ------
extern "C" __global__ void __launch_bounds__(256)
k_agg(const float* __restrict__ feat, const void* __restrict__ srcp,
      float* __restrict__ out)
{
    __shared__ int s_is32;
    const int gid = blockIdx.x * 256 + threadIdx.x;
    if (threadIdx.x == 0) s_is32 = detect32(srcp);
    if (gid < NB_D) g_agg_f[gid] = 0;
    __syncthreads();
    const int is32 = s_is32;

    const int n = gid >> 5;
    const int lane = threadIdx.x & 31;
    if (n >= N_NODES) return;
    if (lane == 0) g_dstcnt[n] = 0;

    const int beg = g_rowoff[n], end = g_rowoff[n + 1];

    float a00 = 0.f, a01 = 0.f, a10 = 0.f, a11 = 0.f;
    float a20 = 0.f, a21 = 0.f, a30 = 0.f, a31 = 0.f;
    float d0 = 0.f, d1 = 0.f, d2 = 0.f, d3 = 0.f;

    int e  = (beg < end) ? g_edst[beg] : 0;
    long long s = (beg < end) ? ldidx(srcp, e, is32) : 0;
    for (int i = beg; i < end; i++) {
        int e_n = (i + 1 < end) ? g_edst[i + 1] : 0;
        float4 p  = *(const float4*)&g_p[e * 4];
        float2 f  = *(const float2*)&feat[s * 64 + 2 * lane];
        long long s_n = (i + 1 < end) ? ldidx(srcp, e_n, is32) : 0;
        a00 += p.x * f.x; a01 += p.x * f.y; d0 += p.x;
        a10 += p.y * f.x; a11 += p.y * f.y; d1 += p.y;
        a20 += p.z * f.x; a21 += p.z * f.y; d2 += p.z;
        a30 += p.w * f.x; a31 += p.w * f.y; d3 += p.w;
        e = e_n; s = s_n;
    }

    float i0 = d0 > 0.f ? __frcp_rn(d0) : 0.f;
    float i1 = d1 > 0.f ? __frcp_rn(d1) : 0.f;
    float i2 = d2 > 0.f ? __frcp_rn(d2) : 0.f;
    float i3 = d3 > 0.f ? __frcp_rn(d3) : 0.f;

    float* o = out + (size_t)n * 256 + 2 * lane;
    *(float2*)(o)       = make_float2(a00 * i0, a01 * i0);
    *(float2*)(o + 64)  = make_float2(a10 * i1, a11 * i1);
    *(float2*)(o + 128) = make_float2(a20 * i2, a21 * i2);
    *(float2*)(o + 192) = make_float2(a30 * i3, a31 * i3);
}

// ---------------- launcher --------------------------------------------------
extern "C" void kernel_launch(void* const* d_in, const int* in_sizes, int n_in,
                              void* d_out, int out_size)
{
    const float* feat  = (const float*)d_in[0];
    const float* qual  = (const float*)d_in[1];
    const float* Wsrc  = (const float*)d_in[2];
    const float* Bsrc  = (const float*)d_in[3];
    const float* Wqual = (const float*)d_in[4];
    const float* Bqual = (const float*)d_in[5];
    const float* attn  = (const float*)d_in[6];
    const void*  src   = d_in[7];
    const void*  dst   = d_in[8];
    const void*  rt    = d_in[9];
    const void*  nid   = d_in[10];
    float* out = (float*)d_out;

    static bool attr_set = false;
    if (!attr_set) {
        cudaFuncSetAttribute(k_score, cudaFuncAttributeMaxDynamicSharedMemorySize,
                             SMEM_SCORE_BYTES);
        attr_set = true;
    }

    k_hist<<<NBLK_HIST, 256>>>(rt, dst);                    // #1
    k_scan<<<NB_D, 1024>>>();                               // #2
    k_scatter<<<NBLK_HIST, 256>>>(rt, dst);                 // #3
    k_score<<<296, 256, SMEM_SCORE_BYTES>>>(feat, qual,     // #4 <- profiled
                                            Wsrc, Bsrc, Wqual, Bqual,
                                            attn, src, nid);
    k_agg<<<(N_NODES * 32 + 255) / 256, 256>>>(feat, src, out);  // #5
}

// round 8
// speedup vs baseline: 1.2456x; 1.0166x over previous
#include <cuda_runtime.h>
#include <cstdint>

#define N_NODES   100000
#define N_REL     8
#define IN_FEATS  64
#define HD        128
#define N_EDGES   800000
#define NEG_SLOPE 0.2f

#define EPB_HIST  1024
#define NBLK_HIST ((N_EDGES + EPB_HIST - 1) / EPB_HIST)   // 782
#define NB_D      ((N_NODES + 1023) / 1024)               // 98

typedef unsigned long long u64;
typedef unsigned int u32;

// ---------------- scratch ---------------------------------------------------
__device__ float g_p[N_EDGES * 4];
__device__ int   g_eorder[N_EDGES];      // edges sorted by relation
__device__ int   g_edst[N_EDGES];        // edges sorted by dst
__device__ int   g_relcnt[8];            // zero-init; re-zeroed by k_scan
__device__ int   g_relcur[8];
__device__ int   g_roff[9];
__device__ int   g_woff[9];              // 32-edge tile offsets per relation
__device__ int   g_dstcnt[N_NODES];      // zero-init; re-zeroed by k_agg
__device__ int   g_rowoff[N_NODES + 1];
__device__ int   g_dstcur[N_NODES];
__device__ int   g_agg_v[NB_D];
__device__ int   g_agg_f[NB_D];          // zero-init; re-zeroed by k_agg

// ---------------- helpers ---------------------------------------------------
__device__ __forceinline__ long long ldidx(const void* p, int i, int is32) {
    return is32 ? (long long)((const int*)p)[i] : ((const long long*)p)[i];
}
__device__ __forceinline__ float lrelu(float v) { return v > 0.0f ? v : NEG_SLOPE * v; }
__device__ __forceinline__ u32 tf32(float f) {
    u32 r; asm("cvt.rna.tf32.f32 %0, %1;" : "=r"(r) : "f"(f)); return r;
}
__device__ __forceinline__ void mma8(float* d, u32 a0, u32 a1, u32 a2, u32 a3,
                                     u32 b0, u32 b1) {
    asm volatile(
        "mma.sync.aligned.m16n8k8.row.col.f32.tf32.tf32.f32 "
        "{%0,%1,%2,%3}, {%4,%5,%6,%7}, {%8,%9}, {%0,%1,%2,%3};"
        : "+f"(d[0]), "+f"(d[1]), "+f"(d[2]), "+f"(d[3])
        : "r"(a0), "r"(a1), "r"(a2), "r"(a3), "r"(b0), "r"(b1));
}
__device__ __forceinline__ void barpair(int id) {
    asm volatile("bar.sync %0, 64;" :: "r"(id) : "memory");
}
__device__ __forceinline__ int detect32(const void* p) {
    const long long* q = (const long long*)p;
    int bad = 0;
    #pragma unroll
    for (int j = 0; j < 16; j++) {
        long long v = q[j];
        if (v < 0 || v >= N_NODES) bad = 1;
    }
    return bad;
}

// ---------------- kernel 1: fused histogram (relation + dst) ----------------
__global__ void k_hist(const void* __restrict__ rtp, const void* __restrict__ dstp) {
    __shared__ int cnt[8];
    __shared__ int s_is32;
    int tid = threadIdx.x;
    if (tid < 8) cnt[tid] = 0;
    if (tid == 0) s_is32 = detect32(dstp);
    __syncthreads();
    const int is32 = s_is32;
    int base = blockIdx.x * EPB_HIST;
    for (int i = tid; i < EPB_HIST; i += 256) {
        int e = base + i;
        if (e < N_EDGES) {
            atomicAdd(&cnt[(int)ldidx(rtp, e, is32)], 1);
            atomicAdd(&g_dstcnt[(int)ldidx(dstp, e, is32)], 1);
        }
    }
    __syncthreads();
    if (tid < 8) atomicAdd(&g_relcnt[tid], cnt[tid]);
}

// ---------------- kernel 2: single-launch dst scan (decoupled lookback) -----
__global__ void __launch_bounds__(1024) k_scan() {
    __shared__ int ws[32];
    __shared__ int s_pred;
    int t = threadIdx.x, b = blockIdx.x;
    int i = b * 1024 + t;
    int v = (i < N_NODES) ? g_dstcnt[i] : 0;
    int lane = t & 31, w = t >> 5;
    int x = v;
    #pragma unroll
    for (int o = 1; o < 32; o <<= 1) {
        int y = __shfl_up_sync(0xffffffffu, x, o);
        if (lane >= o) x += y;
    }
    if (lane == 31) ws[w] = x;
    __syncthreads();
    if (t < 32) {
        int y = ws[t];
        #pragma unroll
        for (int o = 1; o < 32; o <<= 1) {
            int z = __shfl_up_sync(0xffffffffu, y, o);
            if (t >= o) y += z;
        }
        ws[t] = y;
    }
    __syncthreads();
    int excl = x - v + (w ? ws[w - 1] : 0);
    int btot = ws[31];
    if (t == 0) {
        s_pred = 0;
        g_agg_v[b] = btot;
        __threadfence();
        atomicExch(&g_agg_f[b], 1);
    }
    __syncthreads();
    if (t < b) {
        while (atomicAdd(&g_agg_f[t], 0) == 0) {}
        atomicAdd(&s_pred, atomicAdd(&g_agg_v[t], 0));
    }
    __syncthreads();
    int base = s_pred;
    if (i < N_NODES) {
        int val = base + excl;
        g_rowoff[i] = val;
        g_dstcur[i] = val;
    }
    if (b == 0 && t == 0) {
        int ro = 0, wo = 0;
        for (int r = 0; r < 8; r++) {
            int c = g_relcnt[r];
            g_roff[r] = ro; g_relcur[r] = ro; g_woff[r] = wo;
            ro += c; wo += (c + 31) / 32;          // 32-edge tiles
            g_relcnt[r] = 0;
        }
        g_roff[8] = ro; g_woff[8] = wo;
        g_rowoff[N_NODES] = N_EDGES;
    }
}

// ---------------- kernel 3: fused scatter (relation + dst) ------------------
__global__ void k_scatter(const void* __restrict__ rtp, const void* __restrict__ dstp) {
    __shared__ int cnt[8], base[8];
    __shared__ int s_is32;
    int tid = threadIdx.x;
    if (tid < 8) cnt[tid] = 0;
    if (tid == 0) s_is32 = detect32(dstp);
    __syncthreads();
    const int is32 = s_is32;
    int b0 = blockIdx.x * EPB_HIST;
    int rloc[4];
    #pragma unroll
    for (int c = 0; c < 4; c++) {
        int e = b0 + c * 256 + tid;
        rloc[c] = -1;
        if (e < N_EDGES) {
            rloc[c] = (int)ldidx(rtp, e, is32);
            atomicAdd(&cnt[rloc[c]], 1);
            int d = (int)ldidx(dstp, e, is32);
            int pos = atomicAdd(&g_dstcur[d], 1);
            g_edst[pos] = e;
        }
    }
    __syncthreads();
    if (tid < 8) { base[tid] = atomicAdd(&g_relcur[tid], cnt[tid]); cnt[tid] = 0; }
    __syncthreads();
    #pragma unroll
    for (int c = 0; c < 4; c++) {
        if (rloc[c] >= 0) {
            int pos = base[rloc[c]] + atomicAdd(&cnt[rloc[c]], 1);
            g_eorder[pos] = b0 + c * 256 + tid;
        }
    }
}

// ---------------- kernel 4: mma.sync tf32 score, warp-pair tiles ------------
// 2 warps share a 32-edge tile; each warp computes N=64 (its 2 heads).
// Gather is line-coalesced: node ids staged in smem, then 8 consecutive
// lanes fetch one contiguous 128B row-half (4 wavefronts/LDG.128, minimum).
// SMEM (dynamic):
//   Wp0  [8192] u32 frag-packed Wsrc  : 0      .. 32768
//   Wp1  [8192] u32 frag-packed Wqual : 32768  .. 65536
//   A    [4 pairs][32 rows][68] u32   : 65536  .. 100352
//   bsum [128] f32                    : 100352 .. 100864
//   attnf[128] f32                    : 100864 .. 101376
#define OFF_WP0 0
#define OFF_WP1 32768
#define OFF_A   65536
#define OFF_B   100352
#define OFF_AT  100864
#define SMEM_SCORE_BYTES 101376

extern "C" __global__ void __launch_bounds__(256, 2)
k_score(const float* __restrict__ feat, const float* __restrict__ qual,
        const float* __restrict__ Wsrc, const float* __restrict__ Bsrc,
        const float* __restrict__ Wqual, const float* __restrict__ Bqual,
        const float* __restrict__ attn,
        const void* __restrict__ srcp, const void* __restrict__ nidp)
{
    extern __shared__ unsigned char sm[];
    u32*   wp0   = (u32*)(sm + OFF_WP0);
    u32*   wp1   = (u32*)(sm + OFF_WP1);
    float* bsum  = (float*)(sm + OFF_B);
    float* attnf = (float*)(sm + OFF_AT);
    __shared__ int nids[4][2][32];       // [pair][mat][row] staged node ids
    __shared__ int s_is32;

    const int tid   = threadIdx.x;
    const int wid   = tid >> 5, lane = tid & 31;
    const int pair  = wid >> 1;          // 0..3
    const int wpair = wid & 1;           // n-half owned by this warp
    const int ptid  = tid & 63;          // thread id within pair
    const int g = lane >> 2, tg = lane & 3;

    if (tid == 0) s_is32 = detect32(srcp);
    __syncthreads();
    const int is32 = s_is32;

    u32* As = (u32*)(sm + OFF_A) + pair * (32 * 68);
    int* myids = &nids[pair][0][0];

    int woff[9], roff[9];
    #pragma unroll
    for (int i = 0; i < 9; i++) { woff[i] = g_woff[i]; roff[i] = g_roff[i]; }
    const int totalw = woff[8];
    const int wtpb = (totalw + gridDim.x - 1) / gridDim.x;
    const int wt0 = blockIdx.x * wtpb;
    const int wt1 = min(wt0 + wtpb, totalw);
    if (wt0 >= wt1) return;

    for (int r = 0; r < 8; r++) {
        const int lo = max(wt0, woff[r]);
        const int hi = min(wt1, woff[r + 1]);
        if (lo >= hi) continue;

        // ---- pack weights for relation r into fragment-major SMEM ----
        __syncthreads();
        for (int idx = tid; idx < 8192; idx += 256) {
            int w  = idx & 3;
            int ln = (idx >> 2) & 31;
            int nt = (idx >> 7) & 15;
            int k4 = idx >> 11;
            int k  = 16 * k4 + (ln & 3) + 4 * w;
            int n  = 8 * nt + (ln >> 2);
            wp0[idx] = tf32(Wsrc [(r * 64 + k) * 128 + n]);
            wp1[idx] = tf32(Wqual[(r * 64 + k) * 128 + n]);
        }
        if (tid < 128) {
            bsum[tid]  = Bsrc[r * 128 + tid] + Bqual[r * 128 + tid];
            attnf[tid] = attn[r * 128 + tid];
        }
        __syncthreads();

        const int relend = roff[r + 1];

        for (int wt = lo + pair; wt < hi; wt += 4) {
            const int estart = roff[r] + (wt - woff[r]) * 32;

            // ---- stage 64 node ids (mat0: src, mat1: nid) ----
            {
                int pos = min(estart + (ptid & 31), relend - 1);
                int e = g_eorder[pos];
                myids[ptid] = (int)((ptid & 32) ? ldidx(nidp, e, is32)
                                                : ldidx(srcp, e, is32));
            }
            barpair(1 + pair);

            float d[2][8][4];
            #pragma unroll
            for (int mt = 0; mt < 2; mt++)
                #pragma unroll
                for (int nt = 0; nt < 8; nt++)
                    #pragma unroll
                    for (int j = 0; j < 4; j++) d[mt][nt][j] = 0.f;

            #pragma unroll
            for (int mat = 0; mat < 2; mat++) {
                // ---- line-coalesced gather: 8 lanes per 128B row-half ----
                {
                    const float* basep = mat == 0 ? feat : qual;
                    const int* ids = myids + mat * 32;
                    int grp = ptid >> 3;          // 0..7
                    int j   = ptid & 7;           // 16B slot within row-half
                    #pragma unroll
                    for (int i = 0; i < 8; i++) {
                        int rh  = i * 8 + grp;    // row-half 0..63
                        int row = rh >> 1, h = rh & 1;
                        int nd  = ids[row];
                        float4 v = *(const float4*)(basep + (size_t)nd * 64
                                                    + h * 32 + j * 4);
                        uint4 t;
                        t.x = tf32(v.x); t.y = tf32(v.y);
                        t.z = tf32(v.z); t.w = tf32(v.w);
                        *(uint4*)(As + row * 68 + h * 32 + j * 4) = t;
                    }
                }
                barpair(1 + pair);

                // ---- 4 k4-steps x (2 m-tiles x 8 n-tiles) ----
                const uint4* wp = (const uint4*)(mat == 0 ? wp0 : wp1);
                #pragma unroll
                for (int k4 = 0; k4 < 4; k4++) {
                    int c0 = 16 * k4 + tg;
                    u32 a[2][8];
                    #pragma unroll
                    for (int mt = 0; mt < 2; mt++) {
                        int rb = 16 * mt;
                        a[mt][0] = As[(rb + g) * 68 + c0];
                        a[mt][1] = As[(rb + g + 8) * 68 + c0];
                        a[mt][2] = As[(rb + g) * 68 + c0 + 4];
                        a[mt][3] = As[(rb + g + 8) * 68 + c0 + 4];
                        a[mt][4] = As[(rb + g) * 68 + c0 + 8];
                        a[mt][5] = As[(rb + g + 8) * 68 + c0 + 8];
                        a[mt][6] = As[(rb + g) * 68 + c0 + 12];
                        a[mt][7] = As[(rb + g + 8) * 68 + c0 + 12];
                    }
                    #pragma unroll
                    for (int ntl = 0; ntl < 8; ntl++) {
                        int nt = 8 * wpair + ntl;
                        uint4 b = wp[(k4 * 16 + nt) * 32 + lane];
                        #pragma unroll
                        for (int mt = 0; mt < 2; mt++) {
                            mma8(d[mt][ntl], a[mt][0], a[mt][1], a[mt][2], a[mt][3],
                                 b.x, b.y);
                            mma8(d[mt][ntl], a[mt][4], a[mt][5], a[mt][6], a[mt][7],
                                 b.z, b.w);
                        }
                    }
                }
                barpair(1 + pair);   // slab consumed; safe to overwrite
            }

            // ---- epilogue: this warp owns heads {2*wpair, 2*wpair+1} ----
            float slo[2][2] = {{0.f, 0.f}, {0.f, 0.f}};
            float shi[2][2] = {{0.f, 0.f}, {0.f, 0.f}};
            #pragma unroll
            for (int ntl = 0; ntl < 8; ntl++) {
                int hp = ntl >> 2;
                int c = 8 * (8 * wpair + ntl) + 2 * tg;
                float b0 = bsum[c], b1 = bsum[c + 1];
                float a0 = attnf[c], a1 = attnf[c + 1];
                #pragma unroll
                for (int mt = 0; mt < 2; mt++) {
                    slo[mt][hp] += lrelu(d[mt][ntl][0] + b0) * a0
                                 + lrelu(d[mt][ntl][1] + b1) * a1;
                    shi[mt][hp] += lrelu(d[mt][ntl][2] + b0) * a0
                                 + lrelu(d[mt][ntl][3] + b1) * a1;
                }
            }
            #pragma unroll
            for (int off = 1; off <= 2; off <<= 1) {
                #pragma unroll
                for (int mt = 0; mt < 2; mt++)
                    #pragma unroll
                    for (int hp = 0; hp < 2; hp++) {
                        slo[mt][hp] += __shfl_xor_sync(0xffffffffu, slo[mt][hp], off);
                        shi[mt][hp] += __shfl_xor_sync(0xffffffffu, shi[mt][hp], off);
                    }
            }
            if (tg == 0) {
                #pragma unroll
                for (int mt = 0; mt < 2; mt++) {
                    int plo = estart + 16 * mt + g;
                    if (plo < relend) {
                        int e = g_eorder[plo];
                        *(float2*)&g_p[e * 4 + 2 * wpair] =
                            make_float2(expf(slo[mt][0]), expf(slo[mt][1]));
                    }
                    int phi = estart + 16 * mt + g + 8;
                    if (phi < relend) {
                        int e = g_eorder[phi];
                        *(float2*)&g_p[e * 4 + 2 * wpair] =
                            make_float2(expf(shi[mt][0]), expf(shi[mt][1]));
                    }
                }
            }
        }
    }
}

// ---------------- kernel 5: per-node CSR aggregation + counter cleanup ------
extern "C" __global__ void __launch_bounds__(256)
k_agg(const float* __restrict__ feat, const void* __restrict__ srcp,
      float* __restrict__ out)
{
    __shared__ int s_is32;
    const int gid = blockIdx.x * 256 + threadIdx.x;
    if (threadIdx.x == 0) s_is32 = detect32(srcp);
    if (gid < NB_D) g_agg_f[gid] = 0;
    __syncthreads();
    const int is32 = s_is32;

    const int n = gid >> 5;
    const int lane = threadIdx.x & 31;
    if (n >= N_NODES) return;
    if (lane == 0) g_dstcnt[n] = 0;

    const int beg = g_rowoff[n], end = g_rowoff[n + 1];

    float a00 = 0.f, a01 = 0.f, a10 = 0.f, a11 = 0.f;
    float a20 = 0.f, a21 = 0.f, a30 = 0.f, a31 = 0.f;
    float d0 = 0.f, d1 = 0.f, d2 = 0.f, d3 = 0.f;

    int e  = (beg < end) ? g_edst[beg] : 0;
    long long s = (beg < end) ? ldidx(srcp, e, is32) : 0;
    for (int i = beg; i < end; i++) {
        int e_n = (i + 1 < end) ? g_edst[i + 1] : 0;
        float4 p  = *(const float4*)&g_p[e * 4];
        float2 f  = *(const float2*)&feat[s * 64 + 2 * lane];
        long long s_n = (i + 1 < end) ? ldidx(srcp, e_n, is32) : 0;
        a00 += p.x * f.x; a01 += p.x * f.y; d0 += p.x;
        a10 += p.y * f.x; a11 += p.y * f.y; d1 += p.y;
        a20 += p.z * f.x; a21 += p.z * f.y; d2 += p.z;
        a30 += p.w * f.x; a31 += p.w * f.y; d3 += p.w;
        e = e_n; s = s_n;
    }

    float i0 = d0 > 0.f ? __frcp_rn(d0) : 0.f;
    float i1 = d1 > 0.f ? __frcp_rn(d1) : 0.f;
    float i2 = d2 > 0.f ? __frcp_rn(d2) : 0.f;
    float i3 = d3 > 0.f ? __frcp_rn(d3) : 0.f;

    float* o = out + (size_t)n * 256 + 2 * lane;
    *(float2*)(o)       = make_float2(a00 * i0, a01 * i0);
    *(float2*)(o + 64)  = make_float2(a10 * i1, a11 * i1);
    *(float2*)(o + 128) = make_float2(a20 * i2, a21 * i2);
    *(float2*)(o + 192) = make_float2(a30 * i3, a31 * i3);
}

// ---------------- launcher --------------------------------------------------
extern "C" void kernel_launch(void* const* d_in, const int* in_sizes, int n_in,
                              void* d_out, int out_size)
{
    const float* feat  = (const float*)d_in[0];
    const float* qual  = (const float*)d_in[1];
    const float* Wsrc  = (const float*)d_in[2];
    const float* Bsrc  = (const float*)d_in[3];
    const float* Wqual = (const float*)d_in[4];
    const float* Bqual = (const float*)d_in[5];
    const float* attn  = (const float*)d_in[6];
    const void*  src   = d_in[7];
    const void*  dst   = d_in[8];
    const void*  rt    = d_in[9];
    const void*  nid   = d_in[10];
    float* out = (float*)d_out;

    static bool attr_set = false;
    if (!attr_set) {
        cudaFuncSetAttribute(k_score, cudaFuncAttributeMaxDynamicSharedMemorySize,
                             SMEM_SCORE_BYTES);
        attr_set = true;
    }

    k_hist<<<NBLK_HIST, 256>>>(rt, dst);                    // #1
    k_scan<<<NB_D, 1024>>>();                               // #2
    k_scatter<<<NBLK_HIST, 256>>>(rt, dst);                 // #3
    k_score<<<296, 256, SMEM_SCORE_BYTES>>>(feat, qual,     // #4 <- profiled
                                            Wsrc, Bsrc, Wqual, Bqual,
                                            attn, src, nid);
    k_agg<<<(N_NODES * 32 + 255) / 256, 256>>>(feat, src, out);  // #5
}

// round 9
// speedup vs baseline: 1.2950x; 1.0397x over previous
#include <cuda_runtime.h>
#include <cstdint>

#define N_NODES   100000
#define N_REL     8
#define IN_FEATS  64
#define HD        128
#define N_EDGES   800000
#define NEG_SLOPE 0.2f

#define EPB_HIST  1024
#define NBLK_HIST ((N_EDGES + EPB_HIST - 1) / EPB_HIST)   // 782
#define NB_D      ((N_NODES + 1023) / 1024)               // 98

#define NPAIR 6                 // warp pairs per 384-thread block

typedef unsigned long long u64;
typedef unsigned int u32;

// ---------------- scratch ---------------------------------------------------
__device__ float g_p[N_EDGES * 4];
__device__ int   g_eorder[N_EDGES];      // edges sorted by relation
__device__ int   g_edst[N_EDGES];        // edges sorted by dst
__device__ int   g_relcnt[8];            // zero-init; re-zeroed by k_scan
__device__ int   g_relcur[8];
__device__ int   g_roff[9];
__device__ int   g_woff[9];              // 16-edge tile offsets per relation
__device__ int   g_dstcnt[N_NODES];      // zero-init; re-zeroed by k_agg
__device__ int   g_rowoff[N_NODES + 1];
__device__ int   g_dstcur[N_NODES];
__device__ int   g_agg_v[NB_D];
__device__ int   g_agg_f[NB_D];          // zero-init; re-zeroed by k_agg

// ---------------- helpers ---------------------------------------------------
__device__ __forceinline__ long long ldidx(const void* p, int i, int is32) {
    return is32 ? (long long)((const int*)p)[i] : ((const long long*)p)[i];
}
__device__ __forceinline__ float lrelu(float v) { return v > 0.0f ? v : NEG_SLOPE * v; }
__device__ __forceinline__ u32 tf32(float f) {
    u32 r; asm("cvt.rna.tf32.f32 %0, %1;" : "=r"(r) : "f"(f)); return r;
}
__device__ __forceinline__ void mma8(float* d, u32 a0, u32 a1, u32 a2, u32 a3,
                                     u32 b0, u32 b1) {
    asm volatile(
        "mma.sync.aligned.m16n8k8.row.col.f32.tf32.tf32.f32 "
        "{%0,%1,%2,%3}, {%4,%5,%6,%7}, {%8,%9}, {%0,%1,%2,%3};"
        : "+f"(d[0]), "+f"(d[1]), "+f"(d[2]), "+f"(d[3])
        : "r"(a0), "r"(a1), "r"(a2), "r"(a3), "r"(b0), "r"(b1));
}
__device__ __forceinline__ void barpair(int id) {
    asm volatile("bar.sync %0, 64;" :: "r"(id) : "memory");
}
__device__ __forceinline__ int detect32(const void* p) {
    const long long* q = (const long long*)p;
    int bad = 0;
    #pragma unroll
    for (int j = 0; j < 16; j++) {
        long long v = q[j];
        if (v < 0 || v >= N_NODES) bad = 1;
    }
    return bad;
}

// ---------------- kernel 1: fused histogram (relation + dst) ----------------
__global__ void k_hist(const void* __restrict__ rtp, const void* __restrict__ dstp) {
    __shared__ int cnt[8];
    __shared__ int s_is32;
    int tid = threadIdx.x;
    if (tid < 8) cnt[tid] = 0;
    if (tid == 0) s_is32 = detect32(dstp);
    __syncthreads();
    const int is32 = s_is32;
    int base = blockIdx.x * EPB_HIST;
    for (int i = tid; i < EPB_HIST; i += 256) {
        int e = base + i;
        if (e < N_EDGES) {
            atomicAdd(&cnt[(int)ldidx(rtp, e, is32)], 1);
            atomicAdd(&g_dstcnt[(int)ldidx(dstp, e, is32)], 1);
        }
    }
    __syncthreads();
    if (tid < 8) atomicAdd(&g_relcnt[tid], cnt[tid]);
}

// ---------------- kernel 2: single-launch dst scan (decoupled lookback) -----
__global__ void __launch_bounds__(1024) k_scan() {
    __shared__ int ws[32];
    __shared__ int s_pred;
    int t = threadIdx.x, b = blockIdx.x;
    int i = b * 1024 + t;
    int v = (i < N_NODES) ? g_dstcnt[i] : 0;
    int lane = t & 31, w = t >> 5;
    int x = v;
    #pragma unroll
    for (int o = 1; o < 32; o <<= 1) {
        int y = __shfl_up_sync(0xffffffffu, x, o);
        if (lane >= o) x += y;
    }
    if (lane == 31) ws[w] = x;
    __syncthreads();
    if (t < 32) {
        int y = ws[t];
        #pragma unroll
        for (int o = 1; o < 32; o <<= 1) {
            int z = __shfl_up_sync(0xffffffffu, y, o);
            if (t >= o) y += z;
        }
        ws[t] = y;
    }
    __syncthreads();
    int excl = x - v + (w ? ws[w - 1] : 0);
    int btot = ws[31];
    if (t == 0) {
        s_pred = 0;
        g_agg_v[b] = btot;
        __threadfence();
        atomicExch(&g_agg_f[b], 1);
    }
    __syncthreads();
    if (t < b) {
        while (atomicAdd(&g_agg_f[t], 0) == 0) {}
        atomicAdd(&s_pred, atomicAdd(&g_agg_v[t], 0));
    }
    __syncthreads();
    int base = s_pred;
    if (i < N_NODES) {
        int val = base + excl;
        g_rowoff[i] = val;
        g_dstcur[i] = val;
    }
    if (b == 0 && t == 0) {
        int ro = 0, wo = 0;
        for (int r = 0; r < 8; r++) {
            int c = g_relcnt[r];
            g_roff[r] = ro; g_relcur[r] = ro; g_woff[r] = wo;
            ro += c; wo += (c + 15) / 16;          // 16-edge tiles
            g_relcnt[r] = 0;
        }
        g_roff[8] = ro; g_woff[8] = wo;
        g_rowoff[N_NODES] = N_EDGES;
    }
}

// ---------------- kernel 3: fused scatter (relation + dst) ------------------
__global__ void k_scatter(const void* __restrict__ rtp, const void* __restrict__ dstp) {
    __shared__ int cnt[8], base[8];
    __shared__ int s_is32;
    int tid = threadIdx.x;
    if (tid < 8) cnt[tid] = 0;
    if (tid == 0) s_is32 = detect32(dstp);
    __syncthreads();
    const int is32 = s_is32;
    int b0 = blockIdx.x * EPB_HIST;
    int rloc[4];
    #pragma unroll
    for (int c = 0; c < 4; c++) {
        int e = b0 + c * 256 + tid;
        rloc[c] = -1;
        if (e < N_EDGES) {
            rloc[c] = (int)ldidx(rtp, e, is32);
            atomicAdd(&cnt[rloc[c]], 1);
            int d = (int)ldidx(dstp, e, is32);
            int pos = atomicAdd(&g_dstcur[d], 1);
            g_edst[pos] = e;
        }
    }
    __syncthreads();
    if (tid < 8) { base[tid] = atomicAdd(&g_relcur[tid], cnt[tid]); cnt[tid] = 0; }
    __syncthreads();
    #pragma unroll
    for (int c = 0; c < 4; c++) {
        if (rloc[c] >= 0) {
            int pos = base[rloc[c]] + atomicAdd(&cnt[rloc[c]], 1);
            g_eorder[pos] = b0 + c * 256 + tid;
        }
    }
}

// ---------------- kernel 4: mma.sync tf32 score, 384-thread blocks ----------
// 6 warp-pairs per block; a pair owns a 16-edge tile; each warp computes its
// N=64 half (2 heads). 32 accumulator regs/thread -> 2 blocks x 384 thr/SM
// (24 warps, 37.5% occ cap vs 25% before).
// SMEM (dynamic):
//   Wp0  [8192] u32 frag-packed Wsrc  : 0      .. 32768
//   Wp1  [8192] u32 frag-packed Wqual : 32768  .. 65536
//   A    [6 pairs][16 rows][68] u32   : 65536  .. 91648
//   bsum [128] f32                    : 91648  .. 92160
//   attnf[128] f32                    : 92160  .. 92672
#define OFF_WP0 0
#define OFF_WP1 32768
#define OFF_A   65536
#define OFF_B   91648
#define OFF_AT  92160
#define SMEM_SCORE_BYTES 92672

extern "C" __global__ void __launch_bounds__(384, 2)
k_score(const float* __restrict__ feat, const float* __restrict__ qual,
        const float* __restrict__ Wsrc, const float* __restrict__ Bsrc,
        const float* __restrict__ Wqual, const float* __restrict__ Bqual,
        const float* __restrict__ attn,
        const void* __restrict__ srcp, const void* __restrict__ nidp)
{
    extern __shared__ unsigned char sm[];
    u32*   wp0   = (u32*)(sm + OFF_WP0);
    u32*   wp1   = (u32*)(sm + OFF_WP1);
    float* bsum  = (float*)(sm + OFF_B);
    float* attnf = (float*)(sm + OFF_AT);
    __shared__ int nids[NPAIR][32];      // [pair][mat*16+row] staged node ids
    __shared__ int s_is32;

    const int tid   = threadIdx.x;
    const int wid   = tid >> 5, lane = tid & 31;
    const int pair  = wid >> 1;          // 0..5
    const int wpair = wid & 1;           // n-half owned by this warp
    const int ptid  = tid & 63;          // thread id within pair
    const int g = lane >> 2, tg = lane & 3;

    if (tid == 0) s_is32 = detect32(srcp);
    __syncthreads();
    const int is32 = s_is32;

    u32* As = (u32*)(sm + OFF_A) + pair * (16 * 68);
    int* myids = &nids[pair][0];

    int woff[9], roff[9];
    #pragma unroll
    for (int i = 0; i < 9; i++) { woff[i] = g_woff[i]; roff[i] = g_roff[i]; }
    const int totalw = woff[8];
    const int wtpb = (totalw + gridDim.x - 1) / gridDim.x;
    const int wt0 = blockIdx.x * wtpb;
    const int wt1 = min(wt0 + wtpb, totalw);
    if (wt0 >= wt1) return;

    for (int r = 0; r < 8; r++) {
        const int lo = max(wt0, woff[r]);
        const int hi = min(wt1, woff[r + 1]);
        if (lo >= hi) continue;

        // ---- pack weights for relation r into fragment-major SMEM ----
        __syncthreads();
        for (int idx = tid; idx < 8192; idx += 384) {
            int w  = idx & 3;
            int ln = (idx >> 2) & 31;
            int nt = (idx >> 7) & 15;
            int k4 = idx >> 11;
            int k  = 16 * k4 + (ln & 3) + 4 * w;
            int n  = 8 * nt + (ln >> 2);
            wp0[idx] = tf32(Wsrc [(r * 64 + k) * 128 + n]);
            wp1[idx] = tf32(Wqual[(r * 64 + k) * 128 + n]);
        }
        if (tid < 128) {
            bsum[tid]  = Bsrc[r * 128 + tid] + Bqual[r * 128 + tid];
            attnf[tid] = attn[r * 128 + tid];
        }
        __syncthreads();

        const int relend = roff[r + 1];

        for (int wt = lo + pair; wt < hi; wt += NPAIR) {
            const int estart = roff[r] + (wt - woff[r]) * 16;

            // ---- stage 32 node ids (16 src + 16 nid) ----
            if (ptid < 32) {
                int pos = min(estart + (ptid & 15), relend - 1);
                int e = g_eorder[pos];
                myids[ptid] = (int)((ptid & 16) ? ldidx(nidp, e, is32)
                                                : ldidx(srcp, e, is32));
            }
            barpair(1 + pair);

            float d[8][4];
            #pragma unroll
            for (int nt = 0; nt < 8; nt++)
                #pragma unroll
                for (int j = 0; j < 4; j++) d[nt][j] = 0.f;

            #pragma unroll
            for (int mat = 0; mat < 2; mat++) {
                // ---- line-coalesced gather: 8 lanes per 128B row-half ----
                {
                    const float* basep = mat == 0 ? feat : qual;
                    const int* ids = myids + mat * 16;
                    int grp = ptid >> 3;          // 0..7
                    int j   = ptid & 7;           // 16B slot within row-half
                    #pragma unroll
                    for (int i = 0; i < 4; i++) {
                        int rh  = i * 8 + grp;    // row-half 0..31
                        int row = rh >> 1, h = rh & 1;
                        int nd  = ids[row];
                        float4 v = *(const float4*)(basep + (size_t)nd * 64
                                                    + h * 32 + j * 4);
                        uint4 t;
                        t.x = tf32(v.x); t.y = tf32(v.y);
                        t.z = tf32(v.z); t.w = tf32(v.w);
                        *(uint4*)(As + row * 68 + h * 32 + j * 4) = t;
                    }
                }
                barpair(1 + pair);

                // ---- 4 k4-steps x 8 n-tiles ----
                const uint4* wp = (const uint4*)(mat == 0 ? wp0 : wp1);
                #pragma unroll
                for (int k4 = 0; k4 < 4; k4++) {
                    int c0 = 16 * k4 + tg;
                    u32 a0 = As[g * 68 + c0];
                    u32 a1 = As[(g + 8) * 68 + c0];
                    u32 a2 = As[g * 68 + c0 + 4];
                    u32 a3 = As[(g + 8) * 68 + c0 + 4];
                    u32 a4 = As[g * 68 + c0 + 8];
                    u32 a5 = As[(g + 8) * 68 + c0 + 8];
                    u32 a6 = As[g * 68 + c0 + 12];
                    u32 a7 = As[(g + 8) * 68 + c0 + 12];
                    #pragma unroll
                    for (int ntl = 0; ntl < 8; ntl++) {
                        int nt = 8 * wpair + ntl;
                        uint4 b = wp[(k4 * 16 + nt) * 32 + lane];
                        mma8(d[ntl], a0, a1, a2, a3, b.x, b.y);
                        mma8(d[ntl], a4, a5, a6, a7, b.z, b.w);
                    }
                }
                barpair(1 + pair);   // slab consumed; safe to overwrite
            }

            // ---- epilogue: this warp owns heads {2*wpair, 2*wpair+1} ----
            float slo[2] = {0.f, 0.f};
            float shi[2] = {0.f, 0.f};
            #pragma unroll
            for (int ntl = 0; ntl < 8; ntl++) {
                int hp = ntl >> 2;
                int c = 8 * (8 * wpair + ntl) + 2 * tg;
                float b0 = bsum[c], b1 = bsum[c + 1];
                float a0 = attnf[c], a1 = attnf[c + 1];
                slo[hp] += lrelu(d[ntl][0] + b0) * a0 + lrelu(d[ntl][1] + b1) * a1;
                shi[hp] += lrelu(d[ntl][2] + b0) * a0 + lrelu(d[ntl][3] + b1) * a1;
            }
            #pragma unroll
            for (int off = 1; off <= 2; off <<= 1) {
                #pragma unroll
                for (int hp = 0; hp < 2; hp++) {
                    slo[hp] += __shfl_xor_sync(0xffffffffu, slo[hp], off);
                    shi[hp] += __shfl_xor_sync(0xffffffffu, shi[hp], off);
                }
            }
            if (tg == 0) {
                int plo = estart + g;
                if (plo < relend) {
                    int e = g_eorder[plo];
                    *(float2*)&g_p[e * 4 + 2 * wpair] =
                        make_float2(expf(slo[0]), expf(slo[1]));
                }
                int phi = estart + g + 8;
                if (phi < relend) {
                    int e = g_eorder[phi];
                    *(float2*)&g_p[e * 4 + 2 * wpair] =
                        make_float2(expf(shi[0]), expf(shi[1]));
                }
            }
        }
    }
}

// ---------------- kernel 5: per-node CSR aggregation + counter cleanup ------
extern "C" __global__ void __launch_bounds__(256)
k_agg(const float* __restrict__ feat, const void* __restrict__ srcp,
      float* __restrict__ out)
{
    __shared__ int s_is32;
    const int gid = blockIdx.x * 256 + threadIdx.x;
    if (threadIdx.x == 0) s_is32 = detect32(srcp);
    if (gid < NB_D) g_agg_f[gid] = 0;
    __syncthreads();
    const int is32 = s_is32;

    const int n = gid >> 5;
    const int lane = threadIdx.x & 31;
    if (n >= N_NODES) return;
    if (lane == 0) g_dstcnt[n] = 0;

    const int beg = g_rowoff[n], end = g_rowoff[n + 1];

    float a00 = 0.f, a01 = 0.f, a10 = 0.f, a11 = 0.f;
    float a20 = 0.f, a21 = 0.f, a30 = 0.f, a31 = 0.f;
    float d0 = 0.f, d1 = 0.f, d2 = 0.f, d3 = 0.f;

    int e  = (beg < end) ? g_edst[beg] : 0;
    long long s = (beg < end) ? ldidx(srcp, e, is32) : 0;
    for (int i = beg; i < end; i++) {
        int e_n = (i + 1 < end) ? g_edst[i + 1] : 0;
        float4 p  = *(const float4*)&g_p[e * 4];
        float2 f  = *(const float2*)&feat[s * 64 + 2 * lane];
        long long s_n = (i + 1 < end) ? ldidx(srcp, e_n, is32) : 0;
        a00 += p.x * f.x; a01 += p.x * f.y; d0 += p.x;
        a10 += p.y * f.x; a11 += p.y * f.y; d1 += p.y;
        a20 += p.z * f.x; a21 += p.z * f.y; d2 += p.z;
        a30 += p.w * f.x; a31 += p.w * f.y; d3 += p.w;
        e = e_n; s = s_n;
    }

    float i0 = d0 > 0.f ? __frcp_rn(d0) : 0.f;
    float i1 = d1 > 0.f ? __frcp_rn(d1) : 0.f;
    float i2 = d2 > 0.f ? __frcp_rn(d2) : 0.f;
    float i3 = d3 > 0.f ? __frcp_rn(d3) : 0.f;

    float* o = out + (size_t)n * 256 + 2 * lane;
    *(float2*)(o)       = make_float2(a00 * i0, a01 * i0);
    *(float2*)(o + 64)  = make_float2(a10 * i1, a11 * i1);
    *(float2*)(o + 128) = make_float2(a20 * i2, a21 * i2);
    *(float2*)(o + 192) = make_float2(a30 * i3, a31 * i3);
}

// ---------------- launcher --------------------------------------------------
extern "C" void kernel_launch(void* const* d_in, const int* in_sizes, int n_in,
                              void* d_out, int out_size)
{
    const float* feat  = (const float*)d_in[0];
    const float* qual  = (const float*)d_in[1];
    const float* Wsrc  = (const float*)d_in[2];
    const float* Bsrc  = (const float*)d_in[3];
    const float* Wqual = (const float*)d_in[4];
    const float* Bqual = (const float*)d_in[5];
    const float* attn  = (const float*)d_in[6];
    const void*  src   = d_in[7];
    const void*  dst   = d_in[8];
    const void*  rt    = d_in[9];
    const void*  nid   = d_in[10];
    float* out = (float*)d_out;

    static bool attr_set = false;
    if (!attr_set) {
        cudaFuncSetAttribute(k_score, cudaFuncAttributeMaxDynamicSharedMemorySize,
                             SMEM_SCORE_BYTES);
        attr_set = true;
    }

    k_hist<<<NBLK_HIST, 256>>>(rt, dst);                    // #1
    k_scan<<<NB_D, 1024>>>();                               // #2
    k_scatter<<<NBLK_HIST, 256>>>(rt, dst);                 // #3
    k_score<<<296, 384, SMEM_SCORE_BYTES>>>(feat, qual,     // #4 <- profiled
                                            Wsrc, Bsrc, Wqual, Bqual,
                                            attn, src, nid);
    k_agg<<<(N_NODES * 32 + 255) / 256, 256>>>(feat, src, out);  // #5
}

// round 10
// speedup vs baseline: 1.6137x; 1.2461x over previous
#include <cuda_runtime.h>
#include <cstdint>

#define N_NODES   100000
#define N_REL     8
#define IN_FEATS  64
#define HD        128
#define N_EDGES   800000
#define NEG_SLOPE 0.2f

#define EPB_HIST  1024
#define NBLK_HIST ((N_EDGES + EPB_HIST - 1) / EPB_HIST)   // 782
#define NB_D      ((N_NODES + 1023) / 1024)               // 98

#define NPAIR 6                 // warp pairs per 384-thread block

typedef unsigned long long u64;
typedef unsigned int u32;

// ---------------- scratch ---------------------------------------------------
__device__ float g_p[N_EDGES * 4];
__device__ int   g_eorder[N_EDGES];      // edges sorted by relation
__device__ int   g_edst[N_EDGES];        // edges sorted by dst
__device__ int   g_relcnt[8];            // zero-init; re-zeroed by k_scan
__device__ int   g_relcur[8];
__device__ int   g_roff[9];
__device__ int   g_woff[9];              // 16-edge tile offsets per relation
__device__ int   g_dstcnt[N_NODES];      // zero-init; re-zeroed by k_agg
__device__ int   g_rowoff[N_NODES + 1];
__device__ int   g_dstcur[N_NODES];
__device__ int   g_agg_v[NB_D];
__device__ int   g_agg_f[NB_D];          // zero-init; re-zeroed by k_agg

// ---------------- helpers ---------------------------------------------------
__device__ __forceinline__ long long ldidx(const void* p, int i, int is32) {
    return is32 ? (long long)((const int*)p)[i] : ((const long long*)p)[i];
}
__device__ __forceinline__ float lrelu(float v) { return v > 0.0f ? v : NEG_SLOPE * v; }
// pack two floats -> bf16x2 (lo in low 16 bits)
__device__ __forceinline__ u32 bf2(float lo, float hi) {
    u32 r; asm("cvt.rn.bf16x2.f32 %0, %1, %2;" : "=r"(r) : "f"(hi), "f"(lo)); return r;
}
__device__ __forceinline__ void mma16(float* d, u32 a0, u32 a1, u32 a2, u32 a3,
                                      u32 b0, u32 b1) {
    asm volatile(
        "mma.sync.aligned.m16n8k16.row.col.f32.bf16.bf16.f32 "
        "{%0,%1,%2,%3}, {%4,%5,%6,%7}, {%8,%9}, {%0,%1,%2,%3};"
        : "+f"(d[0]), "+f"(d[1]), "+f"(d[2]), "+f"(d[3])
        : "r"(a0), "r"(a1), "r"(a2), "r"(a3), "r"(b0), "r"(b1));
}
__device__ __forceinline__ void barpair(int id) {
    asm volatile("bar.sync %0, 64;" :: "r"(id) : "memory");
}
__device__ __forceinline__ int detect32(const void* p) {
    const long long* q = (const long long*)p;
    int bad = 0;
    #pragma unroll
    for (int j = 0; j < 16; j++) {
        long long v = q[j];
        if (v < 0 || v >= N_NODES) bad = 1;
    }
    return bad;
}

// ---------------- kernel 1: fused histogram (relation + dst) ----------------
__global__ void k_hist(const void* __restrict__ rtp, const void* __restrict__ dstp) {
    __shared__ int cnt[8];
    __shared__ int s_is32;
    int tid = threadIdx.x;
    if (tid < 8) cnt[tid] = 0;
    if (tid == 0) s_is32 = detect32(dstp);
    __syncthreads();
    const int is32 = s_is32;
    int base = blockIdx.x * EPB_HIST;
    for (int i = tid; i < EPB_HIST; i += 256) {
        int e = base + i;
        if (e < N_EDGES) {
            atomicAdd(&cnt[(int)ldidx(rtp, e, is32)], 1);
            atomicAdd(&g_dstcnt[(int)ldidx(dstp, e, is32)], 1);
        }
    }
    __syncthreads();
    if (tid < 8) atomicAdd(&g_relcnt[tid], cnt[tid]);
}

// ---------------- kernel 2: single-launch dst scan (decoupled lookback) -----
__global__ void __launch_bounds__(1024) k_scan() {
    __shared__ int ws[32];
    __shared__ int s_pred;
    int t = threadIdx.x, b = blockIdx.x;
    int i = b * 1024 + t;
    int v = (i < N_NODES) ? g_dstcnt[i] : 0;
    int lane = t & 31, w = t >> 5;
    int x = v;
    #pragma unroll
    for (int o = 1; o < 32; o <<= 1) {
        int y = __shfl_up_sync(0xffffffffu, x, o);
        if (lane >= o) x += y;
    }
    if (lane == 31) ws[w] = x;
    __syncthreads();
    if (t < 32) {
        int y = ws[t];
        #pragma unroll
        for (int o = 1; o < 32; o <<= 1) {
            int z = __shfl_up_sync(0xffffffffu, y, o);
            if (t >= o) y += z;
        }
        ws[t] = y;
    }
    __syncthreads();
    int excl = x - v + (w ? ws[w - 1] : 0);
    int btot = ws[31];
    if (t == 0) {
        s_pred = 0;
        g_agg_v[b] = btot;
        __threadfence();
        atomicExch(&g_agg_f[b], 1);
    }
    __syncthreads();
    if (t < b) {
        while (atomicAdd(&g_agg_f[t], 0) == 0) {}
        atomicAdd(&s_pred, atomicAdd(&g_agg_v[t], 0));
    }
    __syncthreads();
    int base = s_pred;
    if (i < N_NODES) {
        int val = base + excl;
        g_rowoff[i] = val;
        g_dstcur[i] = val;
    }
    if (b == 0 && t == 0) {
        int ro = 0, wo = 0;
        for (int r = 0; r < 8; r++) {
            int c = g_relcnt[r];
            g_roff[r] = ro; g_relcur[r] = ro; g_woff[r] = wo;
            ro += c; wo += (c + 15) / 16;          // 16-edge tiles
            g_relcnt[r] = 0;
        }
        g_roff[8] = ro; g_woff[8] = wo;
        g_rowoff[N_NODES] = N_EDGES;
    }
}

// ---------------- kernel 3: fused scatter (relation + dst) ------------------
__global__ void k_scatter(const void* __restrict__ rtp, const void* __restrict__ dstp) {
    __shared__ int cnt[8], base[8];
    __shared__ int s_is32;
    int tid = threadIdx.x;
    if (tid < 8) cnt[tid] = 0;
    if (tid == 0) s_is32 = detect32(dstp);
    __syncthreads();
    const int is32 = s_is32;
    int b0 = blockIdx.x * EPB_HIST;
    int rloc[4];
    #pragma unroll
    for (int c = 0; c < 4; c++) {
        int e = b0 + c * 256 + tid;
        rloc[c] = -1;
        if (e < N_EDGES) {
            rloc[c] = (int)ldidx(rtp, e, is32);
            atomicAdd(&cnt[rloc[c]], 1);
            int d = (int)ldidx(dstp, e, is32);
            int pos = atomicAdd(&g_dstcur[d], 1);
            g_edst[pos] = e;
        }
    }
    __syncthreads();
    if (tid < 8) { base[tid] = atomicAdd(&g_relcur[tid], cnt[tid]); cnt[tid] = 0; }
    __syncthreads();
    #pragma unroll
    for (int c = 0; c < 4; c++) {
        if (rloc[c] >= 0) {
            int pos = base[rloc[c]] + atomicAdd(&cnt[rloc[c]], 1);
            g_eorder[pos] = b0 + c * 256 + tid;
        }
    }
}

// ---------------- kernel 4: mma.sync bf16 score, 384-thread blocks ----------
// R9 skeleton, bf16 m16n8k16: per-edge B-fragment LDS halves (4KB -> 2KB),
// HMMA count halves, A slab halves. Only datatype/packing/layout changed.
// SMEM (dynamic):
//   Wp0  [4096] u32 frag-packed Wsrc  : 0     .. 16384
//   Wp1  [4096] u32 frag-packed Wqual : 16384 .. 32768
//   A    [6 pairs][16 rows][36] u32   : 32768 .. 46592
//   bsum [128] f32                    : 46592 .. 47104
//   attnf[128] f32                    : 47104 .. 47616
#define OFF_WP0 0
#define OFF_WP1 16384
#define OFF_A   32768
#define OFF_B   46592
#define OFF_AT  47104
#define SMEM_SCORE_BYTES 47616

extern "C" __global__ void __launch_bounds__(384, 2)
k_score(const float* __restrict__ feat, const float* __restrict__ qual,
        const float* __restrict__ Wsrc, const float* __restrict__ Bsrc,
        const float* __restrict__ Wqual, const float* __restrict__ Bqual,
        const float* __restrict__ attn,
        const void* __restrict__ srcp, const void* __restrict__ nidp)
{
    extern __shared__ unsigned char sm[];
    u32*   wp0   = (u32*)(sm + OFF_WP0);
    u32*   wp1   = (u32*)(sm + OFF_WP1);
    float* bsum  = (float*)(sm + OFF_B);
    float* attnf = (float*)(sm + OFF_AT);
    __shared__ int nids[NPAIR][32];      // [pair][mat*16+row] staged node ids
    __shared__ int s_is32;

    const int tid   = threadIdx.x;
    const int wid   = tid >> 5, lane = tid & 31;
    const int pair  = wid >> 1;          // 0..5
    const int wpair = wid & 1;           // n-half owned by this warp
    const int ptid  = tid & 63;          // thread id within pair
    const int g = lane >> 2, tg = lane & 3;

    if (tid == 0) s_is32 = detect32(srcp);
    __syncthreads();
    const int is32 = s_is32;

    u32* As = (u32*)(sm + OFF_A) + pair * (16 * 36);
    int* myids = &nids[pair][0];

    int woff[9], roff[9];
    #pragma unroll
    for (int i = 0; i < 9; i++) { woff[i] = g_woff[i]; roff[i] = g_roff[i]; }
    const int totalw = woff[8];
    const int wtpb = (totalw + gridDim.x - 1) / gridDim.x;
    const int wt0 = blockIdx.x * wtpb;
    const int wt1 = min(wt0 + wtpb, totalw);
    if (wt0 >= wt1) return;

    for (int r = 0; r < 8; r++) {
        const int lo = max(wt0, woff[r]);
        const int hi = min(wt1, woff[r + 1]);
        if (lo >= hi) continue;

        // ---- pack weights for relation r: bf16 fragment-major ----
        __syncthreads();
        for (int idx = tid; idx < 4096; idx += 384) {
            int half = idx & 1;
            int ln   = (idx >> 1) & 31;
            int nt   = (idx >> 6) & 15;
            int ks   = idx >> 10;
            int k = 16 * ks + 2 * (ln & 3) + 8 * half;
            int n = 8 * nt + (ln >> 2);
            const float* w0 = &Wsrc [(r * 64 + k) * 128 + n];
            const float* w1 = &Wqual[(r * 64 + k) * 128 + n];
            wp0[idx] = bf2(w0[0], w0[128]);
            wp1[idx] = bf2(w1[0], w1[128]);
        }
        if (tid < 128) {
            bsum[tid]  = Bsrc[r * 128 + tid] + Bqual[r * 128 + tid];
            attnf[tid] = attn[r * 128 + tid];
        }
        __syncthreads();

        const int relend = roff[r + 1];

        for (int wt = lo + pair; wt < hi; wt += NPAIR) {
            const int estart = roff[r] + (wt - woff[r]) * 16;

            // ---- stage 32 node ids (16 src + 16 nid) ----
            if (ptid < 32) {
                int pos = min(estart + (ptid & 15), relend - 1);
                int e = g_eorder[pos];
                myids[ptid] = (int)((ptid & 16) ? ldidx(nidp, e, is32)
                                                : ldidx(srcp, e, is32));
            }
            barpair(1 + pair);

            float d[8][4];
            #pragma unroll
            for (int nt = 0; nt < 8; nt++)
                #pragma unroll
                for (int j = 0; j < 4; j++) d[nt][j] = 0.f;

            #pragma unroll
            for (int mat = 0; mat < 2; mat++) {
                // ---- line-coalesced gather -> bf16 slab (stride 36 u32) ----
                {
                    const float* basep = mat == 0 ? feat : qual;
                    const int* ids = myids + mat * 16;
                    int grp = ptid >> 3;          // 0..7
                    int j   = ptid & 7;           // 16B src slot within row-half
                    #pragma unroll
                    for (int i = 0; i < 4; i++) {
                        int rh  = i * 8 + grp;    // row-half 0..31
                        int row = rh >> 1, h = rh & 1;
                        int nd  = ids[row];
                        float4 v = *(const float4*)(basep + (size_t)nd * 64
                                                    + h * 32 + j * 4);
                        uint2 t;
                        t.x = bf2(v.x, v.y);
                        t.y = bf2(v.z, v.w);
                        *(uint2*)(As + row * 36 + h * 16 + j * 2) = t;
                    }
                }
                barpair(1 + pair);

                // ---- 4 ks-steps x 8 n-tiles ----
                const uint2* wp = (const uint2*)(mat == 0 ? wp0 : wp1);
                #pragma unroll
                for (int ks = 0; ks < 4; ks++) {
                    int c0 = ks * 8 + tg;
                    u32 a0 = As[g * 36 + c0];
                    u32 a1 = As[(g + 8) * 36 + c0];
                    u32 a2 = As[g * 36 + c0 + 4];
                    u32 a3 = As[(g + 8) * 36 + c0 + 4];
                    #pragma unroll
                    for (int ntl = 0; ntl < 8; ntl++) {
                        int nt = 8 * wpair + ntl;
                        uint2 b = wp[(ks * 16 + nt) * 32 + lane];
                        mma16(d[ntl], a0, a1, a2, a3, b.x, b.y);
                    }
                }
                barpair(1 + pair);   // slab consumed; safe to overwrite
            }

            // ---- epilogue: this warp owns heads {2*wpair, 2*wpair+1} ----
            float slo[2] = {0.f, 0.f};
            float shi[2] = {0.f, 0.f};
            #pragma unroll
            for (int ntl = 0; ntl < 8; ntl++) {
                int hp = ntl >> 2;
                int c = 8 * (8 * wpair + ntl) + 2 * tg;
                float b0 = bsum[c], b1 = bsum[c + 1];
                float a0 = attnf[c], a1 = attnf[c + 1];
                slo[hp] += lrelu(d[ntl][0] + b0) * a0 + lrelu(d[ntl][1] + b1) * a1;
                shi[hp] += lrelu(d[ntl][2] + b0) * a0 + lrelu(d[ntl][3] + b1) * a1;
            }
            #pragma unroll
            for (int off = 1; off <= 2; off <<= 1) {
                #pragma unroll
                for (int hp = 0; hp < 2; hp++) {
                    slo[hp] += __shfl_xor_sync(0xffffffffu, slo[hp], off);
                    shi[hp] += __shfl_xor_sync(0xffffffffu, shi[hp], off);
                }
            }
            if (tg == 0) {
                int plo = estart + g;
                if (plo < relend) {
                    int e = g_eorder[plo];
                    *(float2*)&g_p[e * 4 + 2 * wpair] =
                        make_float2(expf(slo[0]), expf(slo[1]));
                }
                int phi = estart + g + 8;
                if (phi < relend) {
                    int e = g_eorder[phi];
                    *(float2*)&g_p[e * 4 + 2 * wpair] =
                        make_float2(expf(shi[0]), expf(shi[1]));
                }
            }
        }
    }
}

// ---------------- kernel 5: per-node CSR aggregation + counter cleanup ------
extern "C" __global__ void __launch_bounds__(256)
k_agg(const float* __restrict__ feat, const void* __restrict__ srcp,
      float* __restrict__ out)
{
    __shared__ int s_is32;
    const int gid = blockIdx.x * 256 + threadIdx.x;
    if (threadIdx.x == 0) s_is32 = detect32(srcp);
    if (gid < NB_D) g_agg_f[gid] = 0;
    __syncthreads();
    const int is32 = s_is32;

    const int n = gid >> 5;
    const int lane = threadIdx.x & 31;
    if (n >= N_NODES) return;
    if (lane == 0) g_dstcnt[n] = 0;

    const int beg = g_rowoff[n], end = g_rowoff[n + 1];

    float a00 = 0.f, a01 = 0.f, a10 = 0.f, a11 = 0.f;
    float a20 = 0.f, a21 = 0.f, a30 = 0.f, a31 = 0.f;
    float d0 = 0.f, d1 = 0.f, d2 = 0.f, d3 = 0.f;

    int e  = (beg < end) ? g_edst[beg] : 0;
    long long s = (beg < end) ? ldidx(srcp, e, is32) : 0;
    for (int i = beg; i < end; i++) {
        int e_n = (i + 1 < end) ? g_edst[i + 1] : 0;
        float4 p  = *(const float4*)&g_p[e * 4];
        float2 f  = *(const float2*)&feat[s * 64 + 2 * lane];
        long long s_n = (i + 1 < end) ? ldidx(srcp, e_n, is32) : 0;
        a00 += p.x * f.x; a01 += p.x * f.y; d0 += p.x;
        a10 += p.y * f.x; a11 += p.y * f.y; d1 += p.y;
        a20 += p.z * f.x; a21 += p.z * f.y; d2 += p.z;
        a30 += p.w * f.x; a31 += p.w * f.y; d3 += p.w;
        e = e_n; s = s_n;
    }

    float i0 = d0 > 0.f ? __frcp_rn(d0) : 0.f;
    float i1 = d1 > 0.f ? __frcp_rn(d1) : 0.f;
    float i2 = d2 > 0.f ? __frcp_rn(d2) : 0.f;
    float i3 = d3 > 0.f ? __frcp_rn(d3) : 0.f;

    float* o = out + (size_t)n * 256 + 2 * lane;
    *(float2*)(o)       = make_float2(a00 * i0, a01 * i0);
    *(float2*)(o + 64)  = make_float2(a10 * i1, a11 * i1);
    *(float2*)(o + 128) = make_float2(a20 * i2, a21 * i2);
    *(float2*)(o + 192) = make_float2(a30 * i3, a31 * i3);
}

// ---------------- launcher --------------------------------------------------
extern "C" void kernel_launch(void* const* d_in, const int* in_sizes, int n_in,
                              void* d_out, int out_size)
{
    const float* feat  = (const float*)d_in[0];
    const float* qual  = (const float*)d_in[1];
    const float* Wsrc  = (const float*)d_in[2];
    const float* Bsrc  = (const float*)d_in[3];
    const float* Wqual = (const float*)d_in[4];
    const float* Bqual = (const float*)d_in[5];
    const float* attn  = (const float*)d_in[6];
    const void*  src   = d_in[7];
    const void*  dst   = d_in[8];
    const void*  rt    = d_in[9];
    const void*  nid   = d_in[10];
    float* out = (float*)d_out;

    static bool attr_set = false;
    if (!attr_set) {
        cudaFuncSetAttribute(k_score, cudaFuncAttributeMaxDynamicSharedMemorySize,
                             SMEM_SCORE_BYTES);
        attr_set = true;
    }

    k_hist<<<NBLK_HIST, 256>>>(rt, dst);                    // #1
    k_scan<<<NB_D, 1024>>>();                               // #2
    k_scatter<<<NBLK_HIST, 256>>>(rt, dst);                 // #3
    k_score<<<296, 384, SMEM_SCORE_BYTES>>>(feat, qual,     // #4 <- profiled
                                            Wsrc, Bsrc, Wqual, Bqual,
                                            attn, src, nid);
    k_agg<<<(N_NODES * 32 + 255) / 256, 256>>>(feat, src, out);  // #5
}

// round 11
// speedup vs baseline: 1.7715x; 1.0978x over previous
#include <cuda_runtime.h>
#include <cstdint>

#define N_NODES   100000
#define N_REL     8
#define IN_FEATS  64
#define HD        128
#define N_EDGES   800000
#define NEG_SLOPE 0.2f

#define EPB_HIST  1024
#define NBLK_HIST ((N_EDGES + EPB_HIST - 1) / EPB_HIST)   // 782
#define NB_D      ((N_NODES + 1023) / 1024)               // 98

#define NPAIR 6                 // warp pairs per 384-thread block

typedef unsigned long long u64;
typedef unsigned int u32;

// ---------------- scratch ---------------------------------------------------
__device__ float g_p[N_EDGES * 4];
__device__ int   g_eorder[N_EDGES];      // edges sorted by relation
__device__ int   g_edst[N_EDGES];        // edges sorted by dst
__device__ int   g_relcnt[8];            // zero-init; re-zeroed by k_scan
__device__ int   g_relcur[8];
__device__ int   g_roff[9];
__device__ int   g_woff[9];              // 16-edge tile offsets per relation
__device__ int   g_dstcnt[N_NODES];      // zero-init; re-zeroed by k_agg
__device__ int   g_rowoff[N_NODES + 1];
__device__ int   g_dstcur[N_NODES];
__device__ int   g_agg_v[NB_D];
__device__ int   g_agg_f[NB_D];          // zero-init; re-zeroed by k_agg

// ---------------- helpers ---------------------------------------------------
__device__ __forceinline__ long long ldidx(const void* p, int i, int is32) {
    return is32 ? (long long)((const int*)p)[i] : ((const long long*)p)[i];
}
__device__ __forceinline__ float lrelu(float v) { return v > 0.0f ? v : NEG_SLOPE * v; }
// pack two floats -> bf16x2 (lo in low 16 bits)
__device__ __forceinline__ u32 bf2(float lo, float hi) {
    u32 r; asm("cvt.rn.bf16x2.f32 %0, %1, %2;" : "=r"(r) : "f"(hi), "f"(lo)); return r;
}
__device__ __forceinline__ void mma16(float* d, u32 a0, u32 a1, u32 a2, u32 a3,
                                      u32 b0, u32 b1) {
    asm volatile(
        "mma.sync.aligned.m16n8k16.row.col.f32.bf16.bf16.f32 "
        "{%0,%1,%2,%3}, {%4,%5,%6,%7}, {%8,%9}, {%0,%1,%2,%3};"
        : "+f"(d[0]), "+f"(d[1]), "+f"(d[2]), "+f"(d[3])
        : "r"(a0), "r"(a1), "r"(a2), "r"(a3), "r"(b0), "r"(b1));
}
__device__ __forceinline__ void barpair(int id) {
    asm volatile("bar.sync %0, 64;" :: "r"(id) : "memory");
}
__device__ __forceinline__ int detect32(const void* p) {
    const long long* q = (const long long*)p;
    int bad = 0;
    #pragma unroll
    for (int j = 0; j < 16; j++) {
        long long v = q[j];
        if (v < 0 || v >= N_NODES) bad = 1;
    }
    return bad;
}

// ---------------- kernel 1: fused histogram (relation + dst) ----------------
__global__ void k_hist(const void* __restrict__ rtp, const void* __restrict__ dstp) {
    __shared__ int cnt[8];
    __shared__ int s_is32;
    int tid = threadIdx.x;
    if (tid < 8) cnt[tid] = 0;
    if (tid == 0) s_is32 = detect32(dstp);
    __syncthreads();
    const int is32 = s_is32;
    int base = blockIdx.x * EPB_HIST;
    for (int i = tid; i < EPB_HIST; i += 256) {
        int e = base + i;
        if (e < N_EDGES) {
            atomicAdd(&cnt[(int)ldidx(rtp, e, is32)], 1);
            atomicAdd(&g_dstcnt[(int)ldidx(dstp, e, is32)], 1);
        }
    }
    __syncthreads();
    if (tid < 8) atomicAdd(&g_relcnt[tid], cnt[tid]);
}

// ---------------- kernel 2: single-launch dst scan (decoupled lookback) -----
__global__ void __launch_bounds__(1024) k_scan() {
    __shared__ int ws[32];
    __shared__ int s_pred;
    int t = threadIdx.x, b = blockIdx.x;
    int i = b * 1024 + t;
    int v = (i < N_NODES) ? g_dstcnt[i] : 0;
    int lane = t & 31, w = t >> 5;
    int x = v;
    #pragma unroll
    for (int o = 1; o < 32; o <<= 1) {
        int y = __shfl_up_sync(0xffffffffu, x, o);
        if (lane >= o) x += y;
    }
    if (lane == 31) ws[w] = x;
    __syncthreads();
    if (t < 32) {
        int y = ws[t];
        #pragma unroll
        for (int o = 1; o < 32; o <<= 1) {
            int z = __shfl_up_sync(0xffffffffu, y, o);
            if (t >= o) y += z;
        }
        ws[t] = y;
    }
    __syncthreads();
    int excl = x - v + (w ? ws[w - 1] : 0);
    int btot = ws[31];
    if (t == 0) {
        s_pred = 0;
        g_agg_v[b] = btot;
        __threadfence();
        atomicExch(&g_agg_f[b], 1);
    }
    __syncthreads();
    if (t < b) {
        while (atomicAdd(&g_agg_f[t], 0) == 0) {}
        atomicAdd(&s_pred, atomicAdd(&g_agg_v[t], 0));
    }
    __syncthreads();
    int base = s_pred;
    if (i < N_NODES) {
        int val = base + excl;
        g_rowoff[i] = val;
        g_dstcur[i] = val;
    }
    if (b == 0 && t == 0) {
        int ro = 0, wo = 0;
        for (int r = 0; r < 8; r++) {
            int c = g_relcnt[r];
            g_roff[r] = ro; g_relcur[r] = ro; g_woff[r] = wo;
            ro += c; wo += (c + 15) / 16;          // 16-edge tiles
            g_relcnt[r] = 0;
        }
        g_roff[8] = ro; g_woff[8] = wo;
        g_rowoff[N_NODES] = N_EDGES;
    }
}

// ---------------- kernel 3: fused scatter (relation + dst) ------------------
__global__ void k_scatter(const void* __restrict__ rtp, const void* __restrict__ dstp) {
    __shared__ int cnt[8], base[8];
    __shared__ int s_is32;
    int tid = threadIdx.x;
    if (tid < 8) cnt[tid] = 0;
    if (tid == 0) s_is32 = detect32(dstp);
    __syncthreads();
    const int is32 = s_is32;
    int b0 = blockIdx.x * EPB_HIST;
    int rloc[4];
    #pragma unroll
    for (int c = 0; c < 4; c++) {
        int e = b0 + c * 256 + tid;
        rloc[c] = -1;
        if (e < N_EDGES) {
            rloc[c] = (int)ldidx(rtp, e, is32);
            atomicAdd(&cnt[rloc[c]], 1);
            int d = (int)ldidx(dstp, e, is32);
            int pos = atomicAdd(&g_dstcur[d], 1);
            g_edst[pos] = e;
        }
    }
    __syncthreads();
    if (tid < 8) { base[tid] = atomicAdd(&g_relcur[tid], cnt[tid]); cnt[tid] = 0; }
    __syncthreads();
    #pragma unroll
    for (int c = 0; c < 4; c++) {
        if (rloc[c] >= 0) {
            int pos = base[rloc[c]] + atomicAdd(&cnt[rloc[c]], 1);
            g_eorder[pos] = b0 + c * 256 + tid;
        }
    }
}

// ---------------- kernel 4: mma.sync bf16 score, pipelined tiles ------------
// R10 skeleton + latency pipelining: node ids live in registers (shuffle
// lookup), both mats gathered in ONE phase (MLP 8), next tile's ids
// prefetched under the MMAs. 2 barriers/tile instead of 5.
// SMEM (dynamic):
//   Wp0  [4096] u32 frag-packed Wsrc  : 0     .. 16384
//   Wp1  [4096] u32 frag-packed Wqual : 16384 .. 32768
//   A    [6 pairs][2 mats][16][36]u32 : 32768 .. 60416
//   bsum [128] f32                    : 60416 .. 60928
//   attnf[128] f32                    : 60928 .. 61440
#define OFF_WP0 0
#define OFF_WP1 16384
#define OFF_A   32768
#define OFF_B   60416
#define OFF_AT  60928
#define SMEM_SCORE_BYTES 61440

extern "C" __global__ void __launch_bounds__(384, 2)
k_score(const float* __restrict__ feat, const float* __restrict__ qual,
        const float* __restrict__ Wsrc, const float* __restrict__ Bsrc,
        const float* __restrict__ Wqual, const float* __restrict__ Bqual,
        const float* __restrict__ attn,
        const void* __restrict__ srcp, const void* __restrict__ nidp)
{
    extern __shared__ unsigned char sm[];
    u32*   wp0   = (u32*)(sm + OFF_WP0);
    u32*   wp1   = (u32*)(sm + OFF_WP1);
    float* bsum  = (float*)(sm + OFF_B);
    float* attnf = (float*)(sm + OFF_AT);
    __shared__ int s_is32;

    const int tid   = threadIdx.x;
    const int wid   = tid >> 5, lane = tid & 31;
    const int pair  = wid >> 1;          // 0..5
    const int wpair = wid & 1;           // n-half owned by this warp
    const int ptid  = tid & 63;          // thread id within pair
    const int g = lane >> 2, tg = lane & 3;

    if (tid == 0) s_is32 = detect32(srcp);
    __syncthreads();
    const int is32 = s_is32;

    u32* As = (u32*)(sm + OFF_A) + pair * (2 * 16 * 36);

    int woff[9], roff[9];
    #pragma unroll
    for (int i = 0; i < 9; i++) { woff[i] = g_woff[i]; roff[i] = g_roff[i]; }
    const int totalw = woff[8];
    const int wtpb = (totalw + gridDim.x - 1) / gridDim.x;
    const int wt0 = blockIdx.x * wtpb;
    const int wt1 = min(wt0 + wtpb, totalw);
    if (wt0 >= wt1) return;

    for (int r = 0; r < 8; r++) {
        const int lo = max(wt0, woff[r]);
        const int hi = min(wt1, woff[r + 1]);
        if (lo >= hi) continue;

        // ---- pack weights for relation r: bf16 fragment-major ----
        __syncthreads();
        for (int idx = tid; idx < 4096; idx += 384) {
            int half = idx & 1;
            int ln   = (idx >> 1) & 31;
            int nt   = (idx >> 6) & 15;
            int ks   = idx >> 10;
            int k = 16 * ks + 2 * (ln & 3) + 8 * half;
            int n = 8 * nt + (ln >> 2);
            const float* w0 = &Wsrc [(r * 64 + k) * 128 + n];
            const float* w1 = &Wqual[(r * 64 + k) * 128 + n];
            wp0[idx] = bf2(w0[0], w0[128]);
            wp1[idx] = bf2(w1[0], w1[128]);
        }
        if (tid < 128) {
            bsum[tid]  = Bsrc[r * 128 + tid] + Bqual[r * 128 + tid];
            attnf[tid] = attn[r * 128 + tid];
        }
        __syncthreads();

        const int relend = roff[r + 1];
        const int rbase  = roff[r] - woff[r] * 16;

        // prologue: ids for first tile (lane 0-15: src, lane 16-31: nid)
        int myid = 0;
        {
            int est = rbase + (lo + pair) * 16;
            int pos = min(est + (lane & 15), relend - 1);
            int e = g_eorder[pos];
            myid = (int)((lane & 16) ? ldidx(nidp, e, is32)
                                     : ldidx(srcp, e, is32));
        }

        for (int wt = lo + pair; wt < hi; wt += NPAIR) {
            const int estart = rbase + wt * 16;

            // ---- gather BOTH mats (8 independent LDG.128, MLP 8) ----
            {
                int grp = ptid >> 3;          // 0..7
                int j   = ptid & 7;           // 16B slot within row-half
                #pragma unroll
                for (int mat = 0; mat < 2; mat++) {
                    const float* basep = mat == 0 ? feat : qual;
                    #pragma unroll
                    for (int i = 0; i < 4; i++) {
                        int rh  = i * 8 + grp;    // row-half 0..31
                        int row = rh >> 1, h = rh & 1;
                        int nd  = __shfl_sync(0xffffffffu, myid, mat * 16 + row);
                        float4 v = *(const float4*)(basep + (size_t)nd * 64
                                                    + h * 32 + j * 4);
                        uint2 t;
                        t.x = bf2(v.x, v.y);
                        t.y = bf2(v.z, v.w);
                        *(uint2*)(As + mat * 576 + row * 36 + h * 16 + j * 2) = t;
                    }
                }
            }

            // ---- prefetch next tile's ids (hidden under MMA) ----
            int myid_nxt = 0;
            {
                int est2 = rbase + (wt + NPAIR) * 16;
                int pos = min(est2 + (lane & 15), relend - 1);
                pos = max(pos, 0);
                int e = g_eorder[pos];
                myid_nxt = (int)((lane & 16) ? ldidx(nidp, e, is32)
                                             : ldidx(srcp, e, is32));
            }

            barpair(1 + pair);

            // ---- MMAs: 2 mats x 4 ks x 8 n-tiles ----
            float d[8][4];
            #pragma unroll
            for (int nt = 0; nt < 8; nt++)
                #pragma unroll
                for (int j = 0; j < 4; j++) d[nt][j] = 0.f;

            #pragma unroll
            for (int mat = 0; mat < 2; mat++) {
                const uint2* wp = (const uint2*)(mat == 0 ? wp0 : wp1);
                const u32* Am = As + mat * 576;
                #pragma unroll
                for (int ks = 0; ks < 4; ks++) {
                    int c0 = ks * 8 + tg;
                    u32 a0 = Am[g * 36 + c0];
                    u32 a1 = Am[(g + 8) * 36 + c0];
                    u32 a2 = Am[g * 36 + c0 + 4];
                    u32 a3 = Am[(g + 8) * 36 + c0 + 4];
                    #pragma unroll
                    for (int ntl = 0; ntl < 8; ntl++) {
                        int nt = 8 * wpair + ntl;
                        uint2 b = wp[(ks * 16 + nt) * 32 + lane];
                        mma16(d[ntl], a0, a1, a2, a3, b.x, b.y);
                    }
                }
            }
            barpair(1 + pair);   // slab consumed; safe to overwrite next iter

            // ---- epilogue: this warp owns heads {2*wpair, 2*wpair+1} ----
            float slo[2] = {0.f, 0.f};
            float shi[2] = {0.f, 0.f};
            #pragma unroll
            for (int ntl = 0; ntl < 8; ntl++) {
                int hp = ntl >> 2;
                int c = 8 * (8 * wpair + ntl) + 2 * tg;
                float b0 = bsum[c], b1 = bsum[c + 1];
                float a0 = attnf[c], a1 = attnf[c + 1];
                slo[hp] += lrelu(d[ntl][0] + b0) * a0 + lrelu(d[ntl][1] + b1) * a1;
                shi[hp] += lrelu(d[ntl][2] + b0) * a0 + lrelu(d[ntl][3] + b1) * a1;
            }
            #pragma unroll
            for (int off = 1; off <= 2; off <<= 1) {
                #pragma unroll
                for (int hp = 0; hp < 2; hp++) {
                    slo[hp] += __shfl_xor_sync(0xffffffffu, slo[hp], off);
                    shi[hp] += __shfl_xor_sync(0xffffffffu, shi[hp], off);
                }
            }
            if (tg == 0) {
                int plo = estart + g;
                if (plo < relend) {
                    int e = g_eorder[plo];
                    *(float2*)&g_p[e * 4 + 2 * wpair] =
                        make_float2(expf(slo[0]), expf(slo[1]));
                }
                int phi = estart + g + 8;
                if (phi < relend) {
                    int e = g_eorder[phi];
                    *(float2*)&g_p[e * 4 + 2 * wpair] =
                        make_float2(expf(shi[0]), expf(shi[1]));
                }
            }

            myid = myid_nxt;
        }
    }
}

// ---------------- kernel 5: per-node CSR aggregation + counter cleanup ------
extern "C" __global__ void __launch_bounds__(256)
k_agg(const float* __restrict__ feat, const void* __restrict__ srcp,
      float* __restrict__ out)
{
    __shared__ int s_is32;
    const int gid = blockIdx.x * 256 + threadIdx.x;
    if (threadIdx.x == 0) s_is32 = detect32(srcp);
    if (gid < NB_D) g_agg_f[gid] = 0;
    __syncthreads();
    const int is32 = s_is32;

    const int n = gid >> 5;
    const int lane = threadIdx.x & 31;
    if (n >= N_NODES) return;
    if (lane == 0) g_dstcnt[n] = 0;

    const int beg = g_rowoff[n], end = g_rowoff[n + 1];

    float a00 = 0.f, a01 = 0.f, a10 = 0.f, a11 = 0.f;
    float a20 = 0.f, a21 = 0.f, a30 = 0.f, a31 = 0.f;
    float d0 = 0.f, d1 = 0.f, d2 = 0.f, d3 = 0.f;

    int e  = (beg < end) ? g_edst[beg] : 0;
    long long s = (beg < end) ? ldidx(srcp, e, is32) : 0;
    for (int i = beg; i < end; i++) {
        int e_n = (i + 1 < end) ? g_edst[i + 1] : 0;
        float4 p  = *(const float4*)&g_p[e * 4];
        float2 f  = *(const float2*)&feat[s * 64 + 2 * lane];
        long long s_n = (i + 1 < end) ? ldidx(srcp, e_n, is32) : 0;
        a00 += p.x * f.x; a01 += p.x * f.y; d0 += p.x;
        a10 += p.y * f.x; a11 += p.y * f.y; d1 += p.y;
        a20 += p.z * f.x; a21 += p.z * f.y; d2 += p.z;
        a30 += p.w * f.x; a31 += p.w * f.y; d3 += p.w;
        e = e_n; s = s_n;
    }

    float i0 = d0 > 0.f ? __frcp_rn(d0) : 0.f;
    float i1 = d1 > 0.f ? __frcp_rn(d1) : 0.f;
    float i2 = d2 > 0.f ? __frcp_rn(d2) : 0.f;
    float i3 = d3 > 0.f ? __frcp_rn(d3) : 0.f;

    float* o = out + (size_t)n * 256 + 2 * lane;
    *(float2*)(o)       = make_float2(a00 * i0, a01 * i0);
    *(float2*)(o + 64)  = make_float2(a10 * i1, a11 * i1);
    *(float2*)(o + 128) = make_float2(a20 * i2, a21 * i2);
    *(float2*)(o + 192) = make_float2(a30 * i3, a31 * i3);
}

// ---------------- launcher --------------------------------------------------
extern "C" void kernel_launch(void* const* d_in, const int* in_sizes, int n_in,
                              void* d_out, int out_size)
{
    const float* feat  = (const float*)d_in[0];
    const float* qual  = (const float*)d_in[1];
    const float* Wsrc  = (const float*)d_in[2];
    const float* Bsrc  = (const float*)d_in[3];
    const float* Wqual = (const float*)d_in[4];
    const float* Bqual = (const float*)d_in[5];
    const float* attn  = (const float*)d_in[6];
    const void*  src   = d_in[7];
    const void*  dst   = d_in[8];
    const void*  rt    = d_in[9];
    const void*  nid   = d_in[10];
    float* out = (float*)d_out;

    static bool attr_set = false;
    if (!attr_set) {
        cudaFuncSetAttribute(k_score, cudaFuncAttributeMaxDynamicSharedMemorySize,
                             SMEM_SCORE_BYTES);
        attr_set = true;
    }

    k_hist<<<NBLK_HIST, 256>>>(rt, dst);                    // #1
    k_scan<<<NB_D, 1024>>>();                               // #2
    k_scatter<<<NBLK_HIST, 256>>>(rt, dst);                 // #3
    k_score<<<296, 384, SMEM_SCORE_BYTES>>>(feat, qual,     // #4 <- profiled
                                            Wsrc, Bsrc, Wqual, Bqual,
                                            attn, src, nid);
    k_agg<<<(N_NODES * 32 + 255) / 256, 256>>>(feat, src, out);  // #5
}

// round 12
// speedup vs baseline: 1.7850x; 1.0076x over previous
#include <cuda_runtime.h>
#include <cstdint>

#define N_NODES   100000
#define N_REL     8
#define IN_FEATS  64
#define HD        128
#define N_EDGES   800000
#define NEG_SLOPE 0.2f

#define EPB_HIST  1024
#define NBLK_HIST ((N_EDGES + EPB_HIST - 1) / EPB_HIST)   // 782
#define NB_D      ((N_NODES + 1023) / 1024)               // 98

#define NPAIR 6                 // warp pairs per 384-thread block

typedef unsigned long long u64;
typedef unsigned int u32;

// ---------------- scratch ---------------------------------------------------
__device__ float g_p[N_EDGES * 4];
__device__ int   g_eorder[N_EDGES];      // edges sorted by relation
__device__ int   g_edst[N_EDGES];        // edges sorted by dst
__device__ int   g_relcnt[8];            // zero-init; re-zeroed by k_scan
__device__ int   g_relcur[8];
__device__ int   g_roff[9];
__device__ int   g_woff[9];              // 16-edge tile offsets per relation
__device__ int   g_dstcnt[N_NODES];      // zero-init; re-zeroed by k_agg
__device__ int   g_rowoff[N_NODES + 1];
__device__ int   g_dstcur[N_NODES];
__device__ int   g_agg_v[NB_D];
__device__ int   g_agg_f[NB_D];          // zero-init; re-zeroed by k_agg

// ---------------- helpers ---------------------------------------------------
__device__ __forceinline__ long long ldidx(const void* p, int i, int is32) {
    return is32 ? (long long)((const int*)p)[i] : ((const long long*)p)[i];
}
__device__ __forceinline__ float lrelu(float v) { return v > 0.0f ? v : NEG_SLOPE * v; }
// pack two floats -> bf16x2 (lo in low 16 bits)
__device__ __forceinline__ u32 bf2(float lo, float hi) {
    u32 r; asm("cvt.rn.bf16x2.f32 %0, %1, %2;" : "=r"(r) : "f"(hi), "f"(lo)); return r;
}
__device__ __forceinline__ void mma16(float* d, u32 a0, u32 a1, u32 a2, u32 a3,
                                      u32 b0, u32 b1) {
    asm volatile(
        "mma.sync.aligned.m16n8k16.row.col.f32.bf16.bf16.f32 "
        "{%0,%1,%2,%3}, {%4,%5,%6,%7}, {%8,%9}, {%0,%1,%2,%3};"
        : "+f"(d[0]), "+f"(d[1]), "+f"(d[2]), "+f"(d[3])
        : "r"(a0), "r"(a1), "r"(a2), "r"(a3), "r"(b0), "r"(b1));
}
__device__ __forceinline__ void barpair(int id) {
    asm volatile("bar.sync %0, 64;" :: "r"(id) : "memory");
}
__device__ __forceinline__ int detect32(const void* p) {
    const long long* q = (const long long*)p;
    int bad = 0;
    #pragma unroll
    for (int j = 0; j < 16; j++) {
        long long v = q[j];
        if (v < 0 || v >= N_NODES) bad = 1;
    }
    return bad;
}

// ---------------- kernel 1: fused histogram (relation + dst) ----------------
__global__ void k_hist(const void* __restrict__ rtp, const void* __restrict__ dstp) {
    __shared__ int cnt[8];
    __shared__ int s_is32;
    int tid = threadIdx.x;
    if (tid < 8) cnt[tid] = 0;
    if (tid == 0) s_is32 = detect32(dstp);
    __syncthreads();
    const int is32 = s_is32;
    int base = blockIdx.x * EPB_HIST;
    for (int i = tid; i < EPB_HIST; i += 256) {
        int e = base + i;
        if (e < N_EDGES) {
            atomicAdd(&cnt[(int)ldidx(rtp, e, is32)], 1);
            atomicAdd(&g_dstcnt[(int)ldidx(dstp, e, is32)], 1);
        }
    }
    __syncthreads();
    if (tid < 8) atomicAdd(&g_relcnt[tid], cnt[tid]);
}

// ---------------- kernel 2: single-launch dst scan (decoupled lookback) -----
__global__ void __launch_bounds__(1024) k_scan() {
    __shared__ int ws[32];
    __shared__ int s_pred;
    int t = threadIdx.x, b = blockIdx.x;
    int i = b * 1024 + t;
    int v = (i < N_NODES) ? g_dstcnt[i] : 0;
    int lane = t & 31, w = t >> 5;
    int x = v;
    #pragma unroll
    for (int o = 1; o < 32; o <<= 1) {
        int y = __shfl_up_sync(0xffffffffu, x, o);
        if (lane >= o) x += y;
    }
    if (lane == 31) ws[w] = x;
    __syncthreads();
    if (t < 32) {
        int y = ws[t];
        #pragma unroll
        for (int o = 1; o < 32; o <<= 1) {
            int z = __shfl_up_sync(0xffffffffu, y, o);
            if (t >= o) y += z;
        }
        ws[t] = y;
    }
    __syncthreads();
    int excl = x - v + (w ? ws[w - 1] : 0);
    int btot = ws[31];
    if (t == 0) {
        s_pred = 0;
        g_agg_v[b] = btot;
        __threadfence();
        atomicExch(&g_agg_f[b], 1);
    }
    __syncthreads();
    if (t < b) {
        while (atomicAdd(&g_agg_f[t], 0) == 0) {}
        atomicAdd(&s_pred, atomicAdd(&g_agg_v[t], 0));
    }
    __syncthreads();
    int base = s_pred;
    if (i < N_NODES) {
        int val = base + excl;
        g_rowoff[i] = val;
        g_dstcur[i] = val;
    }
    if (b == 0 && t == 0) {
        int ro = 0, wo = 0;
        for (int r = 0; r < 8; r++) {
            int c = g_relcnt[r];
            g_roff[r] = ro; g_relcur[r] = ro; g_woff[r] = wo;
            ro += c; wo += (c + 15) / 16;          // 16-edge tiles
            g_relcnt[r] = 0;
        }
        g_roff[8] = ro; g_woff[8] = wo;
        g_rowoff[N_NODES] = N_EDGES;
    }
}

// ---------------- kernel 3: fused scatter (relation + dst) ------------------
__global__ void k_scatter(const void* __restrict__ rtp, const void* __restrict__ dstp) {
    __shared__ int cnt[8], base[8];
    __shared__ int s_is32;
    int tid = threadIdx.x;
    if (tid < 8) cnt[tid] = 0;
    if (tid == 0) s_is32 = detect32(dstp);
    __syncthreads();
    const int is32 = s_is32;
    int b0 = blockIdx.x * EPB_HIST;
    int rloc[4];
    #pragma unroll
    for (int c = 0; c < 4; c++) {
        int e = b0 + c * 256 + tid;
        rloc[c] = -1;
        if (e < N_EDGES) {
            rloc[c] = (int)ldidx(rtp, e, is32);
            atomicAdd(&cnt[rloc[c]], 1);
            int d = (int)ldidx(dstp, e, is32);
            int pos = atomicAdd(&g_dstcur[d], 1);
            g_edst[pos] = e;
        }
    }
    __syncthreads();
    if (tid < 8) { base[tid] = atomicAdd(&g_relcur[tid], cnt[tid]); cnt[tid] = 0; }
    __syncthreads();
    #pragma unroll
    for (int c = 0; c < 4; c++) {
        if (rloc[c] >= 0) {
            int pos = base[rloc[c]] + atomicAdd(&cnt[rloc[c]], 1);
            g_eorder[pos] = b0 + c * 256 + tid;
        }
    }
}

// ---------------- kernel 4: mma.sync bf16 score, double-buffered pipeline ---
// Per iteration, per mat: LDG(t+1) -> MMA-half(t) -> cvt/STS(t+1). Gather
// latency hides under the HMMAs; ONE barrier per tile (write buf != read buf).
// ids prefetched 2 tiles ahead in registers (shuffle lookup).
// SMEM (dynamic):
//   Wp0  [4096] u32 frag-packed Wsrc       : 0     .. 16384
//   Wp1  [4096] u32 frag-packed Wqual      : 16384 .. 32768
//   A    [6 pairs][2 buf][2 mats][16][36]  : 32768 .. 88064
//   bsum [128] f32                         : 88064 .. 88576
//   attnf[128] f32                         : 88576 .. 89088
#define OFF_WP0 0
#define OFF_WP1 16384
#define OFF_A   32768
#define OFF_B   88064
#define OFF_AT  88576
#define SMEM_SCORE_BYTES 89088

extern "C" __global__ void __launch_bounds__(384, 2)
k_score(const float* __restrict__ feat, const float* __restrict__ qual,
        const float* __restrict__ Wsrc, const float* __restrict__ Bsrc,
        const float* __restrict__ Wqual, const float* __restrict__ Bqual,
        const float* __restrict__ attn,
        const void* __restrict__ srcp, const void* __restrict__ nidp)
{
    extern __shared__ unsigned char sm[];
    u32*   wp0   = (u32*)(sm + OFF_WP0);
    u32*   wp1   = (u32*)(sm + OFF_WP1);
    float* bsum  = (float*)(sm + OFF_B);
    float* attnf = (float*)(sm + OFF_AT);
    __shared__ int s_is32;

    const int tid   = threadIdx.x;
    const int wid   = tid >> 5, lane = tid & 31;
    const int pair  = wid >> 1;          // 0..5
    const int wpair = wid & 1;           // n-half owned by this warp
    const int ptid  = tid & 63;          // thread id within pair
    const int g = lane >> 2, tg = lane & 3;
    const int grp = ptid >> 3;           // 0..7 (gather row-group)
    const int gj  = ptid & 7;            // 16B slot within row-half

    if (tid == 0) s_is32 = detect32(srcp);
    __syncthreads();
    const int is32 = s_is32;

    u32* As = (u32*)(sm + OFF_A) + pair * 2304;   // 2 buf x 1152 u32

    int woff[9], roff[9];
    #pragma unroll
    for (int i = 0; i < 9; i++) { woff[i] = g_woff[i]; roff[i] = g_roff[i]; }
    const int totalw = woff[8];
    const int wtpb = (totalw + gridDim.x - 1) / gridDim.x;
    const int wt0 = blockIdx.x * wtpb;
    const int wt1 = min(wt0 + wtpb, totalw);
    if (wt0 >= wt1) return;

    for (int r = 0; r < 8; r++) {
        const int lo = max(wt0, woff[r]);
        const int hi = min(wt1, woff[r + 1]);
        if (lo >= hi) continue;

        // ---- pack weights for relation r: bf16 fragment-major ----
        __syncthreads();
        for (int idx = tid; idx < 4096; idx += 384) {
            int half = idx & 1;
            int ln   = (idx >> 1) & 31;
            int nt   = (idx >> 6) & 15;
            int ks   = idx >> 10;
            int k = 16 * ks + 2 * (ln & 3) + 8 * half;
            int n = 8 * nt + (ln >> 2);
            const float* w0 = &Wsrc [(r * 64 + k) * 128 + n];
            const float* w1 = &Wqual[(r * 64 + k) * 128 + n];
            wp0[idx] = bf2(w0[0], w0[128]);
            wp1[idx] = bf2(w1[0], w1[128]);
        }
        if (tid < 128) {
            bsum[tid]  = Bsrc[r * 128 + tid] + Bqual[r * 128 + tid];
            attnf[tid] = attn[r * 128 + tid];
        }
        __syncthreads();

        const int relend = roff[r + 1];
        const int rbase  = roff[r] - woff[r] * 16;

        // ---- prologue: ids(t0), gather(t0)->buf0, ids(t0+NPAIR) ----
        int myid;
        {
            int est = rbase + (lo + pair) * 16;
            int pos = min(est + (lane & 15), relend - 1);
            int e = g_eorder[pos];
            myid = (int)((lane & 16) ? ldidx(nidp, e, is32)
                                     : ldidx(srcp, e, is32));
        }
        #pragma unroll
        for (int mat = 0; mat < 2; mat++) {
            const float* basep = mat == 0 ? feat : qual;
            #pragma unroll
            for (int i = 0; i < 4; i++) {
                int rh = i * 8 + grp, row = rh >> 1, h = rh & 1;
                int nd = __shfl_sync(0xffffffffu, myid, mat * 16 + row);
                float4 v = *(const float4*)(basep + (size_t)nd * 64
                                            + h * 32 + gj * 4);
                uint2 t;
                t.x = bf2(v.x, v.y);
                t.y = bf2(v.z, v.w);
                *(uint2*)(As + mat * 576 + row * 36 + h * 16 + gj * 2) = t;
            }
        }
        {
            int est = rbase + (lo + pair + NPAIR) * 16;
            int pos = max(min(est + (lane & 15), relend - 1), 0);
            int e = g_eorder[pos];
            myid = (int)((lane & 16) ? ldidx(nidp, e, is32)
                                     : ldidx(srcp, e, is32));
        }
        barpair(1 + pair);

        int p = 0;
        for (int wt = lo + pair; wt < hi; wt += NPAIR) {
            const int estart = rbase + wt * 16;
            u32* bufc = As + p * 1152;
            u32* bufn = As + (p ^ 1) * 1152;

            float d[8][4];
            #pragma unroll
            for (int nt = 0; nt < 8; nt++)
                #pragma unroll
                for (int j = 0; j < 4; j++) d[nt][j] = 0.f;

            // ---- interleaved: LDG(t+1) | MMA(t) | STS(t+1), per mat ----
            #pragma unroll
            for (int mat = 0; mat < 2; mat++) {
                const float* basep = mat == 0 ? feat : qual;

                // issue gather loads for next tile (latency hides under MMA)
                float4 v[4];
                int rowv[4], hv[4];
                #pragma unroll
                for (int i = 0; i < 4; i++) {
                    int rh = i * 8 + grp;
                    rowv[i] = rh >> 1; hv[i] = rh & 1;
                    int nd = __shfl_sync(0xffffffffu, myid, mat * 16 + rowv[i]);
                    v[i] = *(const float4*)(basep + (size_t)nd * 64
                                            + hv[i] * 32 + gj * 4);
                }

                // MMA half on current buffer
                const uint2* wp = (const uint2*)(mat == 0 ? wp0 : wp1);
                const u32* Am = bufc + mat * 576;
                #pragma unroll
                for (int ks = 0; ks < 4; ks++) {
                    int c0 = ks * 8 + tg;
                    u32 a0 = Am[g * 36 + c0];
                    u32 a1 = Am[(g + 8) * 36 + c0];
                    u32 a2 = Am[g * 36 + c0 + 4];
                    u32 a3 = Am[(g + 8) * 36 + c0 + 4];
                    #pragma unroll
                    for (int ntl = 0; ntl < 8; ntl++) {
                        int nt = 8 * wpair + ntl;
                        uint2 b = wp[(ks * 16 + nt) * 32 + lane];
                        mma16(d[ntl], a0, a1, a2, a3, b.x, b.y);
                    }
                }

                // convert + store next tile's slab half
                #pragma unroll
                for (int i = 0; i < 4; i++) {
                    uint2 t;
                    t.x = bf2(v[i].x, v[i].y);
                    t.y = bf2(v[i].z, v[i].w);
                    *(uint2*)(bufn + mat * 576 + rowv[i] * 36
                              + hv[i] * 16 + gj * 2) = t;
                }
            }

            // ---- prefetch ids two tiles ahead ----
            int myid_nxt;
            {
                int est2 = rbase + (wt + 2 * NPAIR) * 16;
                int pos = max(min(est2 + (lane & 15), relend - 1), 0);
                int e = g_eorder[pos];
                myid_nxt = (int)((lane & 16) ? ldidx(nidp, e, is32)
                                             : ldidx(srcp, e, is32));
            }

            // ---- epilogue: this warp owns heads {2*wpair, 2*wpair+1} ----
            float slo[2] = {0.f, 0.f};
            float shi[2] = {0.f, 0.f};
            #pragma unroll
            for (int ntl = 0; ntl < 8; ntl++) {
                int hp = ntl >> 2;
                int c = 8 * (8 * wpair + ntl) + 2 * tg;
                float b0 = bsum[c], b1 = bsum[c + 1];
                float a0 = attnf[c], a1 = attnf[c + 1];
                slo[hp] += lrelu(d[ntl][0] + b0) * a0 + lrelu(d[ntl][1] + b1) * a1;
                shi[hp] += lrelu(d[ntl][2] + b0) * a0 + lrelu(d[ntl][3] + b1) * a1;
            }
            #pragma unroll
            for (int off = 1; off <= 2; off <<= 1) {
                #pragma unroll
                for (int hp = 0; hp < 2; hp++) {
                    slo[hp] += __shfl_xor_sync(0xffffffffu, slo[hp], off);
                    shi[hp] += __shfl_xor_sync(0xffffffffu, shi[hp], off);
                }
            }
            if (tg == 0) {
                int plo = estart + g;
                if (plo < relend) {
                    int e = g_eorder[plo];
                    *(float2*)&g_p[e * 4 + 2 * wpair] =
                        make_float2(expf(slo[0]), expf(slo[1]));
                }
                int phi = estart + g + 8;
                if (phi < relend) {
                    int e = g_eorder[phi];
                    *(float2*)&g_p[e * 4 + 2 * wpair] =
                        make_float2(expf(shi[0]), expf(shi[1]));
                }
            }

            barpair(1 + pair);    // STS(t+1) visible to partner warp
            myid = myid_nxt;
            p ^= 1;
        }
    }
}

// ---------------- kernel 5: per-node CSR aggregation + counter cleanup ------
extern "C" __global__ void __launch_bounds__(256)
k_agg(const float* __restrict__ feat, const void* __restrict__ srcp,
      float* __restrict__ out)
{
    __shared__ int s_is32;
    const int gid = blockIdx.x * 256 + threadIdx.x;
    if (threadIdx.x == 0) s_is32 = detect32(srcp);
    if (gid < NB_D) g_agg_f[gid] = 0;
    __syncthreads();
    const int is32 = s_is32;

    const int n = gid >> 5;
    const int lane = threadIdx.x & 31;
    if (n >= N_NODES) return;
    if (lane == 0) g_dstcnt[n] = 0;

    const int beg = g_rowoff[n], end = g_rowoff[n + 1];

    float a00 = 0.f, a01 = 0.f, a10 = 0.f, a11 = 0.f;
    float a20 = 0.f, a21 = 0.f, a30 = 0.f, a31 = 0.f;
    float d0 = 0.f, d1 = 0.f, d2 = 0.f, d3 = 0.f;

    int e  = (beg < end) ? g_edst[beg] : 0;
    long long s = (beg < end) ? ldidx(srcp, e, is32) : 0;
    for (int i = beg; i < end; i++) {
        int e_n = (i + 1 < end) ? g_edst[i + 1] : 0;
        float4 p  = *(const float4*)&g_p[e * 4];
        float2 f  = *(const float2*)&feat[s * 64 + 2 * lane];
        long long s_n = (i + 1 < end) ? ldidx(srcp, e_n, is32) : 0;
        a00 += p.x * f.x; a01 += p.x * f.y; d0 += p.x;
        a10 += p.y * f.x; a11 += p.y * f.y; d1 += p.y;
        a20 += p.z * f.x; a21 += p.z * f.y; d2 += p.z;
        a30 += p.w * f.x; a31 += p.w * f.y; d3 += p.w;
        e = e_n; s = s_n;
    }

    float i0 = d0 > 0.f ? __frcp_rn(d0) : 0.f;
    float i1 = d1 > 0.f ? __frcp_rn(d1) : 0.f;
    float i2 = d2 > 0.f ? __frcp_rn(d2) : 0.f;
    float i3 = d3 > 0.f ? __frcp_rn(d3) : 0.f;

    float* o = out + (size_t)n * 256 + 2 * lane;
    *(float2*)(o)       = make_float2(a00 * i0, a01 * i0);
    *(float2*)(o + 64)  = make_float2(a10 * i1, a11 * i1);
    *(float2*)(o + 128) = make_float2(a20 * i2, a21 * i2);
    *(float2*)(o + 192) = make_float2(a30 * i3, a31 * i3);
}

// ---------------- launcher --------------------------------------------------
extern "C" void kernel_launch(void* const* d_in, const int* in_sizes, int n_in,
                              void* d_out, int out_size)
{
    const float* feat  = (const float*)d_in[0];
    const float* qual  = (const float*)d_in[1];
    const float* Wsrc  = (const float*)d_in[2];
    const float* Bsrc  = (const float*)d_in[3];
    const float* Wqual = (const float*)d_in[4];
    const float* Bqual = (const float*)d_in[5];
    const float* attn  = (const float*)d_in[6];
    const void*  src   = d_in[7];
    const void*  dst   = d_in[8];
    const void*  rt    = d_in[9];
    const void*  nid   = d_in[10];
    float* out = (float*)d_out;

    static bool attr_set = false;
    if (!attr_set) {
        cudaFuncSetAttribute(k_score, cudaFuncAttributeMaxDynamicSharedMemorySize,
                             SMEM_SCORE_BYTES);
        attr_set = true;
    }

    k_hist<<<NBLK_HIST, 256>>>(rt, dst);                    // #1
    k_scan<<<NB_D, 1024>>>();                               // #2
    k_scatter<<<NBLK_HIST, 256>>>(rt, dst);                 // #3
    k_score<<<296, 384, SMEM_SCORE_BYTES>>>(feat, qual,     // #4 <- profiled
                                            Wsrc, Bsrc, Wqual, Bqual,
                                            attn, src, nid);
    k_agg<<<(N_NODES * 32 + 255) / 256, 256>>>(feat, src, out);  // #5
}

// round 13
// speedup vs baseline: 2.1044x; 1.1789x over previous
#include <cuda_runtime.h>
#include <cstdint>

#define N_NODES   100000
#define N_REL     8
#define IN_FEATS  64
#define HD        128
#define N_EDGES   800000
#define NEG_SLOPE 0.2f

#define EPB_HIST  1024
#define NBLK_HIST ((N_EDGES + EPB_HIST - 1) / EPB_HIST)   // 782
#define NB_D      ((N_NODES + 1023) / 1024)               // 98

#define NPAIR 6                 // warp pairs per 384-thread block

typedef unsigned long long u64;
typedef unsigned int u32;

// ---------------- scratch ---------------------------------------------------
__device__ float g_p[N_EDGES * 4];       // exp(score), stored in DST order
__device__ int   g_eorder[N_EDGES];      // edges sorted by relation
__device__ int   g_edpos[N_EDGES];       // dst-order slot of each rel-sorted edge
__device__ int   g_srcd[N_EDGES];        // src node id, in dst order
__device__ int   g_relcnt[8];            // zero-init; re-zeroed by k_scan
__device__ int   g_relcur[8];
__device__ int   g_roff[9];
__device__ int   g_woff[9];              // 16-edge tile offsets per relation
__device__ int   g_dstcnt[N_NODES];      // zero-init; re-zeroed by k_agg
__device__ int   g_rowoff[N_NODES + 1];
__device__ int   g_dstcur[N_NODES];
__device__ int   g_agg_v[NB_D];
__device__ int   g_agg_f[NB_D];          // zero-init; re-zeroed by k_agg

// ---------------- helpers ---------------------------------------------------
__device__ __forceinline__ long long ldidx(const void* p, int i, int is32) {
    return is32 ? (long long)((const int*)p)[i] : ((const long long*)p)[i];
}
__device__ __forceinline__ float lrelu(float v) { return v > 0.0f ? v : NEG_SLOPE * v; }
// pack two floats -> bf16x2 (lo in low 16 bits)
__device__ __forceinline__ u32 bf2(float lo, float hi) {
    u32 r; asm("cvt.rn.bf16x2.f32 %0, %1, %2;" : "=r"(r) : "f"(hi), "f"(lo)); return r;
}
__device__ __forceinline__ void mma16(float* d, u32 a0, u32 a1, u32 a2, u32 a3,
                                      u32 b0, u32 b1) {
    asm volatile(
        "mma.sync.aligned.m16n8k16.row.col.f32.bf16.bf16.f32 "
        "{%0,%1,%2,%3}, {%4,%5,%6,%7}, {%8,%9}, {%0,%1,%2,%3};"
        : "+f"(d[0]), "+f"(d[1]), "+f"(d[2]), "+f"(d[3])
        : "r"(a0), "r"(a1), "r"(a2), "r"(a3), "r"(b0), "r"(b1));
}
__device__ __forceinline__ void barpair(int id) {
    asm volatile("bar.sync %0, 64;" :: "r"(id) : "memory");
}
__device__ __forceinline__ int detect32(const void* p) {
    const long long* q = (const long long*)p;
    int bad = 0;
    #pragma unroll
    for (int j = 0; j < 16; j++) {
        long long v = q[j];
        if (v < 0 || v >= N_NODES) bad = 1;
    }
    return bad;
}

// ---------------- kernel 1: fused histogram (relation + dst) ----------------
__global__ void k_hist(const void* __restrict__ rtp, const void* __restrict__ dstp) {
    __shared__ int cnt[8];
    __shared__ int s_is32;
    int tid = threadIdx.x;
    if (tid < 8) cnt[tid] = 0;
    if (tid == 0) s_is32 = detect32(dstp);
    __syncthreads();
    const int is32 = s_is32;
    int base = blockIdx.x * EPB_HIST;
    for (int i = tid; i < EPB_HIST; i += 256) {
        int e = base + i;
        if (e < N_EDGES) {
            atomicAdd(&cnt[(int)ldidx(rtp, e, is32)], 1);
            atomicAdd(&g_dstcnt[(int)ldidx(dstp, e, is32)], 1);
        }
    }
    __syncthreads();
    if (tid < 8) atomicAdd(&g_relcnt[tid], cnt[tid]);
}

// ---------------- kernel 2: single-launch dst scan (decoupled lookback) -----
__global__ void __launch_bounds__(1024) k_scan() {
    __shared__ int ws[32];
    __shared__ int s_pred;
    int t = threadIdx.x, b = blockIdx.x;
    int i = b * 1024 + t;
    int v = (i < N_NODES) ? g_dstcnt[i] : 0;
    int lane = t & 31, w = t >> 5;
    int x = v;
    #pragma unroll
    for (int o = 1; o < 32; o <<= 1) {
        int y = __shfl_up_sync(0xffffffffu, x, o);
        if (lane >= o) x += y;
    }
    if (lane == 31) ws[w] = x;
    __syncthreads();
    if (t < 32) {
        int y = ws[t];
        #pragma unroll
        for (int o = 1; o < 32; o <<= 1) {
            int z = __shfl_up_sync(0xffffffffu, y, o);
            if (t >= o) y += z;
        }
        ws[t] = y;
    }
    __syncthreads();
    int excl = x - v + (w ? ws[w - 1] : 0);
    int btot = ws[31];
    if (t == 0) {
        s_pred = 0;
        g_agg_v[b] = btot;
        __threadfence();
        atomicExch(&g_agg_f[b], 1);
    }
    __syncthreads();
    if (t < b) {
        while (atomicAdd(&g_agg_f[t], 0) == 0) {}
        atomicAdd(&s_pred, atomicAdd(&g_agg_v[t], 0));
    }
    __syncthreads();
    int base = s_pred;
    if (i < N_NODES) {
        int val = base + excl;
        g_rowoff[i] = val;
        g_dstcur[i] = val;
    }
    if (b == 0 && t == 0) {
        int ro = 0, wo = 0;
        for (int r = 0; r < 8; r++) {
            int c = g_relcnt[r];
            g_roff[r] = ro; g_relcur[r] = ro; g_woff[r] = wo;
            ro += c; wo += (c + 15) / 16;          // 16-edge tiles
            g_relcnt[r] = 0;
        }
        g_roff[8] = ro; g_woff[8] = wo;
        g_rowoff[N_NODES] = N_EDGES;
    }
}

// ---------------- kernel 3: fused scatter (relation + dst + srcd) -----------
__global__ void k_scatter(const void* __restrict__ rtp, const void* __restrict__ dstp,
                          const void* __restrict__ srcp) {
    __shared__ int cnt[8], base[8];
    __shared__ int s_is32;
    int tid = threadIdx.x;
    if (tid < 8) cnt[tid] = 0;
    if (tid == 0) s_is32 = detect32(dstp);
    __syncthreads();
    const int is32 = s_is32;
    int b0 = blockIdx.x * EPB_HIST;
    int rloc[4], dloc[4];
    #pragma unroll
    for (int c = 0; c < 4; c++) {
        int e = b0 + c * 256 + tid;
        rloc[c] = -1;
        if (e < N_EDGES) {
            rloc[c] = (int)ldidx(rtp, e, is32);
            atomicAdd(&cnt[rloc[c]], 1);
            int d = (int)ldidx(dstp, e, is32);
            int pos = atomicAdd(&g_dstcur[d], 1);
            dloc[c] = pos;
            g_srcd[pos] = (int)ldidx(srcp, e, is32);   // src id in dst order
        }
    }
    __syncthreads();
    if (tid < 8) { base[tid] = atomicAdd(&g_relcur[tid], cnt[tid]); cnt[tid] = 0; }
    __syncthreads();
    #pragma unroll
    for (int c = 0; c < 4; c++) {
        if (rloc[c] >= 0) {
            int posr = base[rloc[c]] + atomicAdd(&cnt[rloc[c]], 1);
            g_eorder[posr] = b0 + c * 256 + tid;
            g_edpos[posr] = dloc[c];                   // dst slot of this edge
        }
    }
}

// ---------------- kernel 4: mma.sync bf16 score, double-buffered pipeline ---
// Identical compute to R12; epilogue writes p into DST-ORDER slots (g_edpos)
// so k_agg streams contiguously.
// SMEM (dynamic):
//   Wp0  [4096] u32 frag-packed Wsrc       : 0     .. 16384
//   Wp1  [4096] u32 frag-packed Wqual      : 16384 .. 32768
//   A    [6 pairs][2 buf][2 mats][16][36]  : 32768 .. 88064
//   bsum [128] f32                         : 88064 .. 88576
//   attnf[128] f32                         : 88576 .. 89088
#define OFF_WP0 0
#define OFF_WP1 16384
#define OFF_A   32768
#define OFF_B   88064
#define OFF_AT  88576
#define SMEM_SCORE_BYTES 89088

extern "C" __global__ void __launch_bounds__(384, 2)
k_score(const float* __restrict__ feat, const float* __restrict__ qual,
        const float* __restrict__ Wsrc, const float* __restrict__ Bsrc,
        const float* __restrict__ Wqual, const float* __restrict__ Bqual,
        const float* __restrict__ attn,
        const void* __restrict__ srcp, const void* __restrict__ nidp)
{
    extern __shared__ unsigned char sm[];
    u32*   wp0   = (u32*)(sm + OFF_WP0);
    u32*   wp1   = (u32*)(sm + OFF_WP1);
    float* bsum  = (float*)(sm + OFF_B);
    float* attnf = (float*)(sm + OFF_AT);
    __shared__ int s_is32;

    const int tid   = threadIdx.x;
    const int wid   = tid >> 5, lane = tid & 31;
    const int pair  = wid >> 1;          // 0..5
    const int wpair = wid & 1;           // n-half owned by this warp
    const int ptid  = tid & 63;          // thread id within pair
    const int g = lane >> 2, tg = lane & 3;
    const int grp = ptid >> 3;           // 0..7 (gather row-group)
    const int gj  = ptid & 7;            // 16B slot within row-half

    if (tid == 0) s_is32 = detect32(srcp);
    __syncthreads();
    const int is32 = s_is32;

    u32* As = (u32*)(sm + OFF_A) + pair * 2304;   // 2 buf x 1152 u32

    int woff[9], roff[9];
    #pragma unroll
    for (int i = 0; i < 9; i++) { woff[i] = g_woff[i]; roff[i] = g_roff[i]; }
    const int totalw = woff[8];
    const int wtpb = (totalw + gridDim.x - 1) / gridDim.x;
    const int wt0 = blockIdx.x * wtpb;
    const int wt1 = min(wt0 + wtpb, totalw);
    if (wt0 >= wt1) return;

    for (int r = 0; r < 8; r++) {
        const int lo = max(wt0, woff[r]);
        const int hi = min(wt1, woff[r + 1]);
        if (lo >= hi) continue;

        // ---- pack weights for relation r: bf16 fragment-major ----
        __syncthreads();
        for (int idx = tid; idx < 4096; idx += 384) {
            int half = idx & 1;
            int ln   = (idx >> 1) & 31;
            int nt   = (idx >> 6) & 15;
            int ks   = idx >> 10;
            int k = 16 * ks + 2 * (ln & 3) + 8 * half;
            int n = 8 * nt + (ln >> 2);
            const float* w0 = &Wsrc [(r * 64 + k) * 128 + n];
            const float* w1 = &Wqual[(r * 64 + k) * 128 + n];
            wp0[idx] = bf2(w0[0], w0[128]);
            wp1[idx] = bf2(w1[0], w1[128]);
        }
        if (tid < 128) {
            bsum[tid]  = Bsrc[r * 128 + tid] + Bqual[r * 128 + tid];
            attnf[tid] = attn[r * 128 + tid];
        }
        __syncthreads();

        const int relend = roff[r + 1];
        const int rbase  = roff[r] - woff[r] * 16;

        // ---- prologue: ids(t0), gather(t0)->buf0, ids(t0+NPAIR) ----
        int myid;
        {
            int est = rbase + (lo + pair) * 16;
            int pos = min(est + (lane & 15), relend - 1);
            int e = g_eorder[pos];
            myid = (int)((lane & 16) ? ldidx(nidp, e, is32)
                                     : ldidx(srcp, e, is32));
        }
        #pragma unroll
        for (int mat = 0; mat < 2; mat++) {
            const float* basep = mat == 0 ? feat : qual;
            #pragma unroll
            for (int i = 0; i < 4; i++) {
                int rh = i * 8 + grp, row = rh >> 1, h = rh & 1;
                int nd = __shfl_sync(0xffffffffu, myid, mat * 16 + row);
                float4 v = *(const float4*)(basep + (size_t)nd * 64
                                            + h * 32 + gj * 4);
                uint2 t;
                t.x = bf2(v.x, v.y);
                t.y = bf2(v.z, v.w);
                *(uint2*)(As + mat * 576 + row * 36 + h * 16 + gj * 2) = t;
            }
        }
        {
            int est = rbase + (lo + pair + NPAIR) * 16;
            int pos = max(min(est + (lane & 15), relend - 1), 0);
            int e = g_eorder[pos];
            myid = (int)((lane & 16) ? ldidx(nidp, e, is32)
                                     : ldidx(srcp, e, is32));
        }
        barpair(1 + pair);

        int p = 0;
        for (int wt = lo + pair; wt < hi; wt += NPAIR) {
            const int estart = rbase + wt * 16;
            u32* bufc = As + p * 1152;
            u32* bufn = As + (p ^ 1) * 1152;

            float d[8][4];
            #pragma unroll
            for (int nt = 0; nt < 8; nt++)
                #pragma unroll
                for (int j = 0; j < 4; j++) d[nt][j] = 0.f;

            // ---- interleaved: LDG(t+1) | MMA(t) | STS(t+1), per mat ----
            #pragma unroll
            for (int mat = 0; mat < 2; mat++) {
                const float* basep = mat == 0 ? feat : qual;

                // issue gather loads for next tile (latency hides under MMA)
                float4 v[4];
                int rowv[4], hv[4];
                #pragma unroll
                for (int i = 0; i < 4; i++) {
                    int rh = i * 8 + grp;
                    rowv[i] = rh >> 1; hv[i] = rh & 1;
                    int nd = __shfl_sync(0xffffffffu, myid, mat * 16 + rowv[i]);
                    v[i] = *(const float4*)(basep + (size_t)nd * 64
                                            + hv[i] * 32 + gj * 4);
                }

                // MMA half on current buffer
                const uint2* wp = (const uint2*)(mat == 0 ? wp0 : wp1);
                const u32* Am = bufc + mat * 576;
                #pragma unroll
                for (int ks = 0; ks < 4; ks++) {
                    int c0 = ks * 8 + tg;
                    u32 a0 = Am[g * 36 + c0];
                    u32 a1 = Am[(g + 8) * 36 + c0];
                    u32 a2 = Am[g * 36 + c0 + 4];
                    u32 a3 = Am[(g + 8) * 36 + c0 + 4];
                    #pragma unroll
                    for (int ntl = 0; ntl < 8; ntl++) {
                        int nt = 8 * wpair + ntl;
                        uint2 b = wp[(ks * 16 + nt) * 32 + lane];
                        mma16(d[ntl], a0, a1, a2, a3, b.x, b.y);
                    }
                }

                // convert + store next tile's slab half
                #pragma unroll
                for (int i = 0; i < 4; i++) {
                    uint2 t;
                    t.x = bf2(v[i].x, v[i].y);
                    t.y = bf2(v[i].z, v[i].w);
                    *(uint2*)(bufn + mat * 576 + rowv[i] * 36
                              + hv[i] * 16 + gj * 2) = t;
                }
            }

            // ---- prefetch ids two tiles ahead ----
            int myid_nxt;
            {
                int est2 = rbase + (wt + 2 * NPAIR) * 16;
                int pos = max(min(est2 + (lane & 15), relend - 1), 0);
                int e = g_eorder[pos];
                myid_nxt = (int)((lane & 16) ? ldidx(nidp, e, is32)
                                             : ldidx(srcp, e, is32));
            }

            // ---- epilogue: this warp owns heads {2*wpair, 2*wpair+1} ----
            float slo[2] = {0.f, 0.f};
            float shi[2] = {0.f, 0.f};
            #pragma unroll
            for (int ntl = 0; ntl < 8; ntl++) {
                int hp = ntl >> 2;
                int c = 8 * (8 * wpair + ntl) + 2 * tg;
                float b0 = bsum[c], b1 = bsum[c + 1];
                float a0 = attnf[c], a1 = attnf[c + 1];
                slo[hp] += lrelu(d[ntl][0] + b0) * a0 + lrelu(d[ntl][1] + b1) * a1;
                shi[hp] += lrelu(d[ntl][2] + b0) * a0 + lrelu(d[ntl][3] + b1) * a1;
            }
            #pragma unroll
            for (int off = 1; off <= 2; off <<= 1) {
                #pragma unroll
                for (int hp = 0; hp < 2; hp++) {
                    slo[hp] += __shfl_xor_sync(0xffffffffu, slo[hp], off);
                    shi[hp] += __shfl_xor_sync(0xffffffffu, shi[hp], off);
                }
            }
            if (tg == 0) {
                int plo = estart + g;
                if (plo < relend) {
                    int dp = g_edpos[plo];
                    *(float2*)&g_p[dp * 4 + 2 * wpair] =
                        make_float2(expf(slo[0]), expf(slo[1]));
                }
                int phi = estart + g + 8;
                if (phi < relend) {
                    int dp = g_edpos[phi];
                    *(float2*)&g_p[dp * 4 + 2 * wpair] =
                        make_float2(expf(shi[0]), expf(shi[1]));
                }
            }

            barpair(1 + pair);    // STS(t+1) visible to partner warp
            myid = myid_nxt;
            p ^= 1;
        }
    }
}

// ---------------- kernel 5: per-node CSR aggregation (streaming) ------------
// g_p and g_srcd are already in dst order: all loads contiguous except feat.
extern "C" __global__ void __launch_bounds__(256)
k_agg(const float* __restrict__ feat, float* __restrict__ out)
{
    const int gid = blockIdx.x * 256 + threadIdx.x;
    if (gid < NB_D) g_agg_f[gid] = 0;            // reset scan flags for replay

    const int n = gid >> 5;                      // node id (warp per node)
    const int lane = threadIdx.x & 31;
    if (n >= N_NODES) return;
    if (lane == 0) g_dstcnt[n] = 0;              // reset histogram for replay

    const int beg = g_rowoff[n], end = g_rowoff[n + 1];

    float a00 = 0.f, a01 = 0.f, a10 = 0.f, a11 = 0.f;
    float a20 = 0.f, a21 = 0.f, a30 = 0.f, a31 = 0.f;
    float d0 = 0.f, d1 = 0.f, d2 = 0.f, d3 = 0.f;

    int s = (beg < end) ? g_srcd[beg] : 0;
    for (int i = beg; i < end; i++) {
        int s_n = (i + 1 < end) ? g_srcd[i + 1] : 0;
        float4 p = ((const float4*)g_p)[i];
        float2 f = *(const float2*)&feat[(size_t)s * 64 + 2 * lane];
        a00 += p.x * f.x; a01 += p.x * f.y; d0 += p.x;
        a10 += p.y * f.x; a11 += p.y * f.y; d1 += p.y;
        a20 += p.z * f.x; a21 += p.z * f.y; d2 += p.z;
        a30 += p.w * f.x; a31 += p.w * f.y; d3 += p.w;
        s = s_n;
    }

    float i0 = d0 > 0.f ? __frcp_rn(d0) : 0.f;
    float i1 = d1 > 0.f ? __frcp_rn(d1) : 0.f;
    float i2 = d2 > 0.f ? __frcp_rn(d2) : 0.f;
    float i3 = d3 > 0.f ? __frcp_rn(d3) : 0.f;

    float* o = out + (size_t)n * 256 + 2 * lane;
    *(float2*)(o)       = make_float2(a00 * i0, a01 * i0);
    *(float2*)(o + 64)  = make_float2(a10 * i1, a11 * i1);
    *(float2*)(o + 128) = make_float2(a20 * i2, a21 * i2);
    *(float2*)(o + 192) = make_float2(a30 * i3, a31 * i3);
}

// ---------------- launcher --------------------------------------------------
extern "C" void kernel_launch(void* const* d_in, const int* in_sizes, int n_in,
                              void* d_out, int out_size)
{
    const float* feat  = (const float*)d_in[0];
    const float* qual  = (const float*)d_in[1];
    const float* Wsrc  = (const float*)d_in[2];
    const float* Bsrc  = (const float*)d_in[3];
    const float* Wqual = (const float*)d_in[4];
    const float* Bqual = (const float*)d_in[5];
    const float* attn  = (const float*)d_in[6];
    const void*  src   = d_in[7];
    const void*  dst   = d_in[8];
    const void*  rt    = d_in[9];
    const void*  nid   = d_in[10];
    float* out = (float*)d_out;

    static bool attr_set = false;
    if (!attr_set) {
        cudaFuncSetAttribute(k_score, cudaFuncAttributeMaxDynamicSharedMemorySize,
                             SMEM_SCORE_BYTES);
        attr_set = true;
    }

    k_hist<<<NBLK_HIST, 256>>>(rt, dst);                    // #1
    k_scan<<<NB_D, 1024>>>();                               // #2
    k_scatter<<<NBLK_HIST, 256>>>(rt, dst, src);            // #3
    k_score<<<296, 384, SMEM_SCORE_BYTES>>>(feat, qual,     // #4 <- profiled
                                            Wsrc, Bsrc, Wqual, Bqual,
                                            attn, src, nid);
    k_agg<<<(N_NODES * 32 + 255) / 256, 256>>>(feat, out);  // #5
}